// round 2
// baseline (speedup 1.0000x reference)
#include <cuda_runtime.h>
#include <math.h>

#define BB 4
#define CC 64
#define HH 192
#define WW 192
#define NN (HH*WW)          // 36864
#define PP (BB*NN)          // 147456
#define NHEADS 2

// ---------------- scratch (device globals; no allocation APIs) ----------------
__device__ float g_t0[BB*CC*NN];
__device__ float g_t1[BB*CC*NN];
__device__ float g_x1[BB*CC*NN];
__device__ float g_q [BB*CC*NN];
__device__ float g_k [BB*CC*NN];
__device__ float g_v [BB*CC*NN];
__device__ float g_o1[BB*CC*NN];
__device__ float g_o2[BB*CC*NN];
__device__ float g_o3[BB*CC*NN];
__device__ float g_s [BB*HH*WW*WW];      // 113 MB, reused for row then col
__device__ float g_norm[2*BB*CC];
__device__ float g_attn[BB*NHEADS*32*32];

__device__ __forceinline__ float gelu_f(float v){
    return 0.5f*v*(1.f+erff(v*0.70710678118654752f));
}

// ---------------- generic 1x1 conv: out[b,o,n] = sum_c w[o,c] in[b,c,n] (+bias) ----------------
template<bool BIAS>
__global__ void conv1x1_k(const float* __restrict__ in, const float* __restrict__ w,
                          const float* __restrict__ bias, float* __restrict__ out){
    __shared__ float ws[CC*CC];
    __shared__ float bs[CC];
    for (int i=threadIdx.x;i<CC*CC;i+=blockDim.x) ws[i]=w[i];
    if (threadIdx.x<CC) bs[threadIdx.x] = BIAS ? bias[threadIdx.x] : 0.f;
    __syncthreads();
    int p = blockIdx.x*blockDim.x+threadIdx.x;
    if (p>=PP) return;
    int b=p/NN, n=p%NN;
    const float* ib = in + (size_t)b*CC*NN + n;
    float acc[CC];
    #pragma unroll
    for (int o=0;o<CC;o++) acc[o]=bs[o];
    #pragma unroll 1
    for (int c=0;c<CC;c+=4){
        float x0=ib[(size_t)(c+0)*NN], x1=ib[(size_t)(c+1)*NN];
        float x2=ib[(size_t)(c+2)*NN], x3=ib[(size_t)(c+3)*NN];
        #pragma unroll
        for (int o=0;o<CC;o++){
            float4 wv = *(const float4*)&ws[o*CC+c];
            acc[o] += wv.x*x0+wv.y*x1+wv.z*x2+wv.w*x3;
        }
    }
    float* ob = out + (size_t)b*CC*NN + n;
    #pragma unroll
    for (int o=0;o<CC;o++) ob[(size_t)o*NN]=acc[o];
}

// ---------------- depthwise 3x3 + bias ----------------
__global__ void dwconv_k(const float* __restrict__ in, const float* __restrict__ w,
                         const float* __restrict__ bias, float* __restrict__ out){
    int idx = blockIdx.x*blockDim.x + threadIdx.x;
    if (idx >= BB*CC*NN) return;
    int n = idx % NN; int bc = idx / NN; int c = bc % CC;
    int y = n / WW, x = n % WW;
    const float* wp = w + c*9;
    const float* ip = in + (size_t)bc*NN;
    float acc = bias[c];
    #pragma unroll
    for (int ky=0;ky<3;ky++){
        int yy = y+ky-1; if (yy<0||yy>=HH) continue;
        #pragma unroll
        for (int kx=0;kx<3;kx++){
            int xx = x+kx-1; if (xx<0||xx>=WW) continue;
            acc += wp[ky*3+kx]*ip[(size_t)yy*WW+xx];
        }
    }
    out[idx] = acc;
}

// ---------------- x1 = conv2(gelu(t1)) + conv0(x) + biases ----------------
__global__ void x1_k(const float* __restrict__ t1, const float* __restrict__ x,
                     const float* __restrict__ w2, const float* __restrict__ b2,
                     const float* __restrict__ w0, const float* __restrict__ b0,
                     float* __restrict__ out){
    __shared__ float ws2[CC*CC], ws0[CC*CC];
    __shared__ float bs[CC];
    for (int i=threadIdx.x;i<CC*CC;i+=blockDim.x){ ws2[i]=w2[i]; ws0[i]=w0[i]; }
    if (threadIdx.x<CC) bs[threadIdx.x]=b2[threadIdx.x]+b0[threadIdx.x];
    __syncthreads();
    int p = blockIdx.x*blockDim.x+threadIdx.x;
    if (p>=PP) return;
    int b=p/NN, n=p%NN;
    const float* tb = t1 + (size_t)b*CC*NN + n;
    const float* xb = x  + (size_t)b*CC*NN + n;
    float acc[CC];
    #pragma unroll
    for (int o=0;o<CC;o++) acc[o]=bs[o];
    #pragma unroll 1
    for (int c=0;c<CC;c+=4){
        float g0=gelu_f(tb[(size_t)(c+0)*NN]), g1=gelu_f(tb[(size_t)(c+1)*NN]);
        float g2=gelu_f(tb[(size_t)(c+2)*NN]), g3=gelu_f(tb[(size_t)(c+3)*NN]);
        float x0=xb[(size_t)(c+0)*NN], x1v=xb[(size_t)(c+1)*NN];
        float x2=xb[(size_t)(c+2)*NN], x3=xb[(size_t)(c+3)*NN];
        #pragma unroll
        for (int o=0;o<CC;o++){
            float4 w2v = *(const float4*)&ws2[o*CC+c];
            float4 w0v = *(const float4*)&ws0[o*CC+c];
            acc[o] += w2v.x*g0+w2v.y*g1+w2v.z*g2+w2v.w*g3
                    + w0v.x*x0+w0v.y*x1v+w0v.z*x2+w0v.w*x3;
        }
    }
    float* ob = out + (size_t)b*CC*NN + n;
    #pragma unroll
    for (int o=0;o<CC;o++) ob[(size_t)o*NN]=acc[o];
}

// ---------------- row-wise sum of squares for q,k (per (tensor,b,channel)) ----------------
__global__ void norm_k(const float* __restrict__ q, const float* __restrict__ k){
    int id = blockIdx.x;                 // 0..2*BB*CC-1
    const float* src = (id < BB*CC) ? q : k;
    int bc = id % (BB*CC);
    const float* r = src + (size_t)bc*NN;
    float s=0.f;
    for (int n=threadIdx.x;n<NN;n+=256){ float v=r[n]; s+=v*v; }
    __shared__ float red[256];
    red[threadIdx.x]=s; __syncthreads();
    for (int o=128;o;o>>=1){ if(threadIdx.x<o) red[threadIdx.x]+=red[threadIdx.x+o]; __syncthreads(); }
    if (threadIdx.x==0) g_norm[id]=red[0];
}

__global__ void zero_attn_k(){
    int i = blockIdx.x*blockDim.x+threadIdx.x;
    if (i < BB*NHEADS*32*32) g_attn[i]=0.f;
}

// ---------------- channel-attn gram: g_attn[b,g,c,d] += sum_n q*k (chunked, atomics) ----------------
#define NCHUNK 32
#define CHUNK (NN/NCHUNK)   // 1152
__global__ void gram_k(const float* __restrict__ q, const float* __restrict__ k){
    int bg = blockIdx.x; int b=bg/NHEADS, g=bg%NHEADS;
    int n0 = blockIdx.y*CHUNK;
    __shared__ float qs[64][33], ks[64][33];
    int c = threadIdx.x>>3, dg = threadIdx.x&7;
    float a0=0,a1=0,a2=0,a3=0;
    const float* qb = q + ((size_t)(b*CC + g*32))*NN + n0;
    const float* kb = k + ((size_t)(b*CC + g*32))*NN + n0;
    for (int tt=0;tt<CHUNK;tt+=64){
        __syncthreads();
        for (int e=threadIdx.x;e<32*64;e+=256){
            int cc=e>>6, t=e&63;
            qs[t][cc]=qb[(size_t)cc*NN + tt + t];
            ks[t][cc]=kb[(size_t)cc*NN + tt + t];
        }
        __syncthreads();
        #pragma unroll 8
        for (int t=0;t<64;t++){
            float qv=qs[t][c];
            a0+=qv*ks[t][dg];    a1+=qv*ks[t][dg+8];
            a2+=qv*ks[t][dg+16]; a3+=qv*ks[t][dg+24];
        }
    }
    float* ab = g_attn + ((size_t)(bg*32+c))*32;
    atomicAdd(&ab[dg],a0);    atomicAdd(&ab[dg+8],a1);
    atomicAdd(&ab[dg+16],a2); atomicAdd(&ab[dg+24],a3);
}

// ---------------- channel-attn finalize: normalize, *temp, softmax over d ----------------
__global__ void chsm_k(const float* __restrict__ temp){
    int bg = blockIdx.x; int b=bg/NHEADS, g=bg%NHEADS;
    int c = threadIdx.x>>5, d = threadIdx.x&31;
    float nq = fmaxf(sqrtf(g_norm[b*CC + g*32 + c]), 1e-12f);
    float nk = fmaxf(sqrtf(g_norm[BB*CC + b*CC + g*32 + d]), 1e-12f);
    int idx = (bg*32+c)*32+d;
    float v = g_attn[idx]/(nq*nk)*temp[g];
    float m=v;
    #pragma unroll
    for (int o=16;o;o>>=1) m=fmaxf(m,__shfl_xor_sync(0xffffffffu,m,o));
    float e=expf(v-m), s=e;
    #pragma unroll
    for (int o=16;o;o>>=1) s+=__shfl_xor_sync(0xffffffffu,s,o);
    g_attn[idx]=e/s;
}

// ---------------- mid = attn @ v (per pixel) ----------------
__global__ void attnv_k(const float* __restrict__ v, float* __restrict__ mid){
    __shared__ float as[NHEADS*32*32];
    int b = blockIdx.x/(NN/256);
    int n = (blockIdx.x%(NN/256))*256 + threadIdx.x;
    for (int i=threadIdx.x;i<NHEADS*32*32;i+=256) as[i]=g_attn[b*NHEADS*32*32+i];
    __syncthreads();
    const float* vb = v + (size_t)b*CC*NN + n;
    float* mb = mid + (size_t)b*CC*NN + n;
    #pragma unroll
    for (int g=0;g<NHEADS;g++){
        float vv[32];
        #pragma unroll
        for (int d=0;d<32;d++) vv[d]=vb[(size_t)(g*32+d)*NN];
        #pragma unroll 1
        for (int c=0;c<32;c++){
            const float* ar = &as[(g*32+c)*32];
            float a=0.f;
            #pragma unroll
            for (int d=0;d<32;d++) a+=ar[d]*vv[d];
            mb[(size_t)(g*32+c)*NN]=a;
        }
    }
}

// ---------------- row gram: s[b,h,i,j] = sum_c Q[b,c,h,i] K[b,c,h,j] ----------------
__global__ void rowgram_k(const float* __restrict__ Q, const float* __restrict__ K,
                          float* __restrict__ s){
    int b = blockIdx.x/HH, h = blockIdx.x%HH;
    __shared__ float qs[CC][WW];    // 48KB
    const float* qb = Q + (size_t)b*CC*NN + (size_t)h*WW;
    for (int e=threadIdx.x;e<CC*WW;e+=192){ int c=e/WW, i=e%WW; qs[c][i]=qb[(size_t)c*NN+i]; }
    int j = threadIdx.x;
    float kr[CC];
    const float* kb = K + (size_t)b*CC*NN + (size_t)h*WW + j;
    #pragma unroll
    for (int c=0;c<CC;c++) kr[c]=kb[(size_t)c*NN];
    __syncthreads();
    float* sb = s + (size_t)blockIdx.x*WW*WW + j;
    #pragma unroll 1
    for (int i=0;i<WW;i+=4){
        float a0=0,a1=0,a2=0,a3=0;
        #pragma unroll
        for (int c=0;c<CC;c++){
            float4 qv=*(const float4*)&qs[c][i];
            float kv=kr[c];
            a0+=qv.x*kv; a1+=qv.y*kv; a2+=qv.z*kv; a3+=qv.w*kv;
        }
        sb[(size_t)(i+0)*WW]=a0; sb[(size_t)(i+1)*WW]=a1;
        sb[(size_t)(i+2)*WW]=a2; sb[(size_t)(i+3)*WW]=a3;
    }
}

// ---------------- col gram: s[b,w,i,j] = sum_c Q[b,c,i,w] K[b,c,j,w] ----------------
__global__ void colgram_k(const float* __restrict__ Q, const float* __restrict__ K,
                          float* __restrict__ s){
    int b = blockIdx.x/WW, w = blockIdx.x%WW;
    __shared__ float qs[CC][HH];    // 48KB
    const float* qb = Q + (size_t)b*CC*NN + w;
    for (int e=threadIdx.x;e<CC*HH;e+=192){ int c=e/HH, i=e%HH; qs[c][i]=qb[(size_t)c*NN+(size_t)i*WW]; }
    int j = threadIdx.x;
    float kr[CC];
    const float* kb = K + (size_t)b*CC*NN + w + (size_t)j*WW;
    #pragma unroll
    for (int c=0;c<CC;c++) kr[c]=kb[(size_t)c*NN];
    __syncthreads();
    float* sb = s + (size_t)blockIdx.x*HH*HH + j;
    #pragma unroll 1
    for (int i=0;i<HH;i+=4){
        float a0=0,a1=0,a2=0,a3=0;
        #pragma unroll
        for (int c=0;c<CC;c++){
            float4 qv=*(const float4*)&qs[c][i];
            float kv=kr[c];
            a0+=qv.x*kv; a1+=qv.y*kv; a2+=qv.z*kv; a3+=qv.w*kv;
        }
        sb[(size_t)(i+0)*HH]=a0; sb[(size_t)(i+1)*HH]=a1;
        sb[(size_t)(i+2)*HH]=a2; sb[(size_t)(i+3)*HH]=a3;
    }
}

// ---------------- softmax over last dim (rows of length 192) ----------------
__global__ void smrow_k(float* __restrict__ s){
    int row  = blockIdx.x*8 + (threadIdx.x>>5);
    int lane = threadIdx.x&31;
    float* r = s + (size_t)row*WW;
    float v[6];
    #pragma unroll
    for (int u=0;u<6;u++) v[u]=r[lane+u*32];
    float m=v[0];
    #pragma unroll
    for (int u=1;u<6;u++) m=fmaxf(m,v[u]);
    #pragma unroll
    for (int o=16;o;o>>=1) m=fmaxf(m,__shfl_xor_sync(0xffffffffu,m,o));
    float sum=0.f;
    #pragma unroll
    for (int u=0;u<6;u++){ v[u]=expf(v[u]-m); sum+=v[u]; }
    #pragma unroll
    for (int o=16;o;o>>=1) sum+=__shfl_xor_sync(0xffffffffu,sum,o);
    float inv=1.f/sum;
    #pragma unroll
    for (int u=0;u<6;u++) r[lane+u*32]=v[u]*inv;
}

// ---------------- row out: out[b,c,h,i] = gamma * sum_j V[b,c,h,j] a[b,h,i,j] + x1 ----------------
__global__ void rowout_k(const float* __restrict__ V, const float* __restrict__ s,
                         const float* __restrict__ x1, const float* __restrict__ gamma_p,
                         float* __restrict__ out){
    extern __shared__ float sm[];
    float* vs = sm;                 // [CC][WW]
    float* as = sm + CC*WW;         // [WW][36]
    int b=blockIdx.x/HH, h=blockIdx.x%HH;
    const float* vb = V + (size_t)b*CC*NN + (size_t)h*WW;
    for (int e=threadIdx.x;e<CC*WW;e+=192){ int c=e/WW, jj=e%WW; vs[c*WW+jj]=vb[(size_t)c*NN+jj]; }
    float gm = gamma_p[0];
    int i = threadIdx.x;
    float acc[CC];
    #pragma unroll
    for (int c=0;c<CC;c++) acc[c]=0.f;
    const float* sb = s + (size_t)blockIdx.x*WW*WW;
    for (int j0=0;j0<WW;j0+=32){
        __syncthreads();
        for (int e=threadIdx.x;e<WW*32;e+=192){ int ii=e>>5, jt=e&31; as[ii*36+jt]=sb[(size_t)ii*WW + j0+jt]; }
        __syncthreads();
        #pragma unroll 1
        for (int jt=0;jt<32;jt++){
            float av=as[i*36+jt];
            #pragma unroll
            for (int c=0;c<CC;c++) acc[c]+=vs[c*WW + j0+jt]*av;
        }
    }
    const float* xb = x1 + (size_t)b*CC*NN + (size_t)h*WW + i;
    float* ob = out + (size_t)b*CC*NN + (size_t)h*WW + i;
    #pragma unroll
    for (int c=0;c<CC;c++) ob[(size_t)c*NN]=gm*acc[c]+xb[(size_t)c*NN];
}

// ---------------- col out: out[b,c,i,w] = gamma * sum_j V[b,c,j,w] a[b,w,i,j] + x1 ----------------
__global__ void colout_k(const float* __restrict__ V, const float* __restrict__ s,
                         const float* __restrict__ x1, const float* __restrict__ gamma_p,
                         float* __restrict__ out){
    extern __shared__ float sm[];
    float* vs = sm;                 // [CC][HH]
    float* as = sm + CC*HH;         // [HH][36]
    int b=blockIdx.x/WW, w=blockIdx.x%WW;
    const float* vb = V + (size_t)b*CC*NN + w;
    for (int e=threadIdx.x;e<CC*HH;e+=192){ int c=e/HH, jj=e%HH; vs[c*HH+jj]=vb[(size_t)c*NN+(size_t)jj*WW]; }
    float gm = gamma_p[0];
    int i = threadIdx.x;
    float acc[CC];
    #pragma unroll
    for (int c=0;c<CC;c++) acc[c]=0.f;
    const float* sb = s + (size_t)blockIdx.x*HH*HH;
    for (int j0=0;j0<HH;j0+=32){
        __syncthreads();
        for (int e=threadIdx.x;e<HH*32;e+=192){ int ii=e>>5, jt=e&31; as[ii*36+jt]=sb[(size_t)ii*HH + j0+jt]; }
        __syncthreads();
        #pragma unroll 1
        for (int jt=0;jt<32;jt++){
            float av=as[i*36+jt];
            #pragma unroll
            for (int c=0;c<CC;c++) acc[c]+=vs[c*HH + j0+jt]*av;
        }
    }
    const float* xb = x1 + (size_t)b*CC*NN + (size_t)i*WW + w;
    float* ob = out + (size_t)b*CC*NN + (size_t)i*WW + w;
    #pragma unroll
    for (int c=0;c<CC;c++) ob[(size_t)c*NN]=gm*acc[c]+xb[(size_t)c*NN];
}

// ---------------- final: out = gelu(conv_w @ [o1;o2;o3] + conv_b) ----------------
__global__ void final_k(const float* __restrict__ o1, const float* __restrict__ o2,
                        const float* __restrict__ o3, const float* __restrict__ w,
                        const float* __restrict__ bias, float* __restrict__ out){
    extern __shared__ float sm[];
    float* ws = sm;                 // [CC][192]
    float* bs = sm + CC*192;
    for (int i=threadIdx.x;i<CC*192;i+=blockDim.x) ws[i]=w[i];
    if (threadIdx.x<CC) bs[threadIdx.x]=bias[threadIdx.x];
    __syncthreads();
    int p = blockIdx.x*blockDim.x+threadIdx.x;
    if (p>=PP) return;
    int b=p/NN, n=p%NN;
    float acc[CC];
    #pragma unroll
    for (int o=0;o<CC;o++) acc[o]=bs[o];
    const float* srcs[3]={o1,o2,o3};
    #pragma unroll
    for (int part=0;part<3;part++){
        const float* ib = srcs[part] + (size_t)b*CC*NN + n;
        #pragma unroll 1
        for (int c=0;c<CC;c+=4){
            float x0=ib[(size_t)(c+0)*NN], x1=ib[(size_t)(c+1)*NN];
            float x2=ib[(size_t)(c+2)*NN], x3=ib[(size_t)(c+3)*NN];
            #pragma unroll
            for (int o=0;o<CC;o++){
                float4 wv = *(const float4*)&ws[o*192 + part*CC + c];
                acc[o] += wv.x*x0+wv.y*x1+wv.z*x2+wv.w*x3;
            }
        }
    }
    float* ob = out + (size_t)b*CC*NN + n;
    #pragma unroll
    for (int o=0;o<CC;o++) ob[(size_t)o*NN]=gelu_f(acc[o]);
}

// =======================================================================
extern "C" void kernel_launch(void* const* d_in, const int* in_sizes, int n_in,
                              void* d_out, int out_size){
    const float* x      =(const float*)d_in[0];
    const float* pw_w   =(const float*)d_in[1];
    const float* dw_w   =(const float*)d_in[2];
    const float* dw_b   =(const float*)d_in[3];
    const float* conv2_w=(const float*)d_in[4];
    const float* conv2_b=(const float*)d_in[5];
    const float* conv0_w=(const float*)d_in[6];
    const float* conv0_b=(const float*)d_in[7];
    const float* att_q_w=(const float*)d_in[8];
    const float* att_k_w=(const float*)d_in[9];
    const float* att_v_w=(const float*)d_in[10];
    const float* att_p_w=(const float*)d_in[11];
    const float* temp   =(const float*)d_in[12];
    const float* row_q_w=(const float*)d_in[13];
    const float* row_k_w=(const float*)d_in[14];
    const float* row_v_w=(const float*)d_in[15];
    const float* row_g  =(const float*)d_in[16];
    const float* col_q_w=(const float*)d_in[17];
    const float* col_k_w=(const float*)d_in[18];
    const float* col_v_w=(const float*)d_in[19];
    const float* col_g  =(const float*)d_in[20];
    const float* conv_w =(const float*)d_in[21];
    const float* conv_b =(const float*)d_in[22];
    float* out=(float*)d_out;

    float *t0,*t1,*x1b,*q,*k,*v,*o1,*o2,*o3,*s;
    cudaGetSymbolAddress((void**)&t0,  g_t0);
    cudaGetSymbolAddress((void**)&t1,  g_t1);
    cudaGetSymbolAddress((void**)&x1b, g_x1);
    cudaGetSymbolAddress((void**)&q,   g_q);
    cudaGetSymbolAddress((void**)&k,   g_k);
    cudaGetSymbolAddress((void**)&v,   g_v);
    cudaGetSymbolAddress((void**)&o1,  g_o1);
    cudaGetSymbolAddress((void**)&o2,  g_o2);
    cudaGetSymbolAddress((void**)&o3,  g_o3);
    cudaGetSymbolAddress((void**)&s,   g_s);

    const int SM_ROWOUT = (CC*WW + WW*36)*4;   // 76800 B
    const int SM_FINAL  = (CC*192 + CC)*4;     // 49408 B
    cudaFuncSetAttribute(rowout_k, cudaFuncAttributeMaxDynamicSharedMemorySize, SM_ROWOUT);
    cudaFuncSetAttribute(colout_k, cudaFuncAttributeMaxDynamicSharedMemorySize, SM_ROWOUT);
    cudaFuncSetAttribute(final_k,  cudaFuncAttributeMaxDynamicSharedMemorySize, SM_FINAL);

    // ---- BSConvU + skip -> x1 ----
    zero_attn_k<<<32,256>>>();
    conv1x1_k<false><<<PP/256,256>>>(x, pw_w, nullptr, t0);
    dwconv_k<<<(BB*CC*NN)/256,256>>>(t0, dw_w, dw_b, t1);
    x1_k<<<PP/256,256>>>(t1, x, conv2_w, conv2_b, conv0_w, conv0_b, x1b);

    // ---- channel self-attention -> o1 ----
    conv1x1_k<false><<<PP/256,256>>>(x1b, att_q_w, nullptr, q);
    conv1x1_k<false><<<PP/256,256>>>(x1b, att_k_w, nullptr, k);
    conv1x1_k<false><<<PP/256,256>>>(x1b, att_v_w, nullptr, v);
    norm_k<<<2*BB*CC,256>>>(q,k);
    gram_k<<<dim3(BB*NHEADS,NCHUNK),256>>>(q,k);
    chsm_k<<<BB*NHEADS,1024>>>(temp);
    attnv_k<<<PP/256,256>>>(v, t0);
    conv1x1_k<false><<<PP/256,256>>>(t0, att_p_w, nullptr, o1);

    // ---- row attention -> o2 ----
    conv1x1_k<false><<<PP/256,256>>>(x1b, row_q_w, nullptr, q);
    conv1x1_k<false><<<PP/256,256>>>(x1b, row_k_w, nullptr, k);
    conv1x1_k<false><<<PP/256,256>>>(o1,  row_v_w, nullptr, v);
    rowgram_k<<<BB*HH,192>>>(q,k,s);
    smrow_k<<<(BB*HH*WW)/8,256>>>(s);
    rowout_k<<<BB*HH,192,SM_ROWOUT>>>(v,s,x1b,row_g,o2);

    // ---- col attention -> o3 ----
    conv1x1_k<false><<<PP/256,256>>>(x1b, col_q_w, nullptr, q);
    conv1x1_k<false><<<PP/256,256>>>(x1b, col_k_w, nullptr, k);
    conv1x1_k<false><<<PP/256,256>>>(o1,  col_v_w, nullptr, v);
    colgram_k<<<BB*WW,192>>>(q,k,s);
    smrow_k<<<(BB*WW*HH)/8,256>>>(s);
    colout_k<<<BB*WW,192,SM_ROWOUT>>>(v,s,x1b,col_g,o3);

    // ---- fuse ----
    final_k<<<PP/256,256,SM_FINAL>>>(o1,o2,o3,conv_w,conv_b,out);
}

// round 5
// speedup vs baseline: 1.4177x; 1.4177x over previous
#include <cuda_runtime.h>
#include <math.h>

#define BB 4
#define CC 64
#define HH 192
#define WW 192
#define NN (HH*WW)          // 36864
#define N4 (NN/4)           // 9216
#define PP (BB*NN)          // 147456
#define NHEADS 2

// ---------------- scratch (device globals; no allocation APIs) ----------------
__device__ float g_t0[BB*CC*NN];
__device__ float g_t1[BB*CC*NN];
__device__ float g_x1[BB*CC*NN];
__device__ float g_q [BB*CC*NN];
__device__ float g_k [BB*CC*NN];
__device__ float g_v [BB*CC*NN];
__device__ float g_o1[BB*CC*NN];
__device__ float g_o2[BB*CC*NN];
__device__ float g_o3[BB*CC*NN];
__device__ float g_s [BB*HH*WW*WW];      // 113 MB, reused row then col
__device__ float g_norm[2*BB*CC];
__device__ float g_attn[BB*NHEADS*32*32];

__device__ __forceinline__ float gelu_f(float v){
    return 0.5f*v*(1.f+erff(v*0.70710678118654752f));
}

// =====================================================================
// Fast 1x1 conv: thread = 16 out-channels x 4 pixels.  grid(NN/256, BB)
// =====================================================================
template<bool BIAS>
__global__ __launch_bounds__(256,2)
void convf_k(const float* __restrict__ in, const float* __restrict__ w,
             const float* __restrict__ bias, float* __restrict__ out){
    __shared__ float4 ws[CC*16];          // [o][c4]
    __shared__ float  bs[CC];
    for (int i=threadIdx.x;i<CC*16;i+=256) ws[i]=((const float4*)w)[i];
    if (BIAS && threadIdx.x<CC) bs[threadIdx.x]=bias[threadIdx.x];
    __syncthreads();
    const float4* in4 = (const float4*)(in + (size_t)blockIdx.y*CC*NN);
    float4*       ou4 = (float4*)(out + (size_t)blockIdx.y*CC*NN);
    int og  = threadIdx.x>>6;
    int base= blockIdx.x*64 + (threadIdx.x&63);    // float4 pixel index
    float4 acc[16];
    #pragma unroll
    for (int o=0;o<16;o++){ float bv = BIAS? bs[og*16+o]:0.f; acc[o]=make_float4(bv,bv,bv,bv); }
    float4 X[4], Xn[4];
    #pragma unroll
    for (int u=0;u<4;u++) X[u]=in4[(size_t)u*N4+base];
    #pragma unroll 1
    for (int c=0;c<CC;c+=4){
        if (c+4<CC){
            #pragma unroll
            for (int u=0;u<4;u++) Xn[u]=in4[(size_t)(c+4+u)*N4+base];
        }
        #pragma unroll
        for (int o=0;o<16;o++){
            float4 wv = ws[(og*16+o)*16 + (c>>2)];
            acc[o].x += wv.x*X[0].x + wv.y*X[1].x + wv.z*X[2].x + wv.w*X[3].x;
            acc[o].y += wv.x*X[0].y + wv.y*X[1].y + wv.z*X[2].y + wv.w*X[3].y;
            acc[o].z += wv.x*X[0].z + wv.y*X[1].z + wv.z*X[2].z + wv.w*X[3].z;
            acc[o].w += wv.x*X[0].w + wv.y*X[1].w + wv.z*X[2].w + wv.w*X[3].w;
        }
        #pragma unroll
        for (int u=0;u<4;u++) X[u]=Xn[u];
    }
    #pragma unroll
    for (int o=0;o<16;o++) ou4[(size_t)(og*16+o)*N4+base]=acc[o];
}

// ---------------- x1 = conv2(gelu_t1) + conv0(x) + b2 + b0 ----------------
__global__ __launch_bounds__(256,2)
void x1f_k(const float* __restrict__ tg, const float* __restrict__ x,
           const float* __restrict__ w2, const float* __restrict__ b2,
           const float* __restrict__ w0, const float* __restrict__ b0,
           float* __restrict__ out){
    __shared__ float4 ws2[CC*16], ws0[CC*16];
    __shared__ float bs[CC];
    for (int i=threadIdx.x;i<CC*16;i+=256){ ws2[i]=((const float4*)w2)[i]; ws0[i]=((const float4*)w0)[i]; }
    if (threadIdx.x<CC) bs[threadIdx.x]=b2[threadIdx.x]+b0[threadIdx.x];
    __syncthreads();
    const float4* t4 = (const float4*)(tg + (size_t)blockIdx.y*CC*NN);
    const float4* x4 = (const float4*)(x  + (size_t)blockIdx.y*CC*NN);
    float4*       ou4= (float4*)(out + (size_t)blockIdx.y*CC*NN);
    int og  = threadIdx.x>>6;
    int base= blockIdx.x*64 + (threadIdx.x&63);
    float4 acc[16];
    #pragma unroll
    for (int o=0;o<16;o++){ float bv=bs[og*16+o]; acc[o]=make_float4(bv,bv,bv,bv); }
    #pragma unroll 1
    for (int c=0;c<CC;c+=4){
        float4 X[4], Y[4];
        #pragma unroll
        for (int u=0;u<4;u++){ X[u]=t4[(size_t)(c+u)*N4+base]; Y[u]=x4[(size_t)(c+u)*N4+base]; }
        #pragma unroll
        for (int o=0;o<16;o++){
            float4 w2v = ws2[(og*16+o)*16 + (c>>2)];
            float4 w0v = ws0[(og*16+o)*16 + (c>>2)];
            acc[o].x += w2v.x*X[0].x + w2v.y*X[1].x + w2v.z*X[2].x + w2v.w*X[3].x
                      + w0v.x*Y[0].x + w0v.y*Y[1].x + w0v.z*Y[2].x + w0v.w*Y[3].x;
            acc[o].y += w2v.x*X[0].y + w2v.y*X[1].y + w2v.z*X[2].y + w2v.w*X[3].y
                      + w0v.x*Y[0].y + w0v.y*Y[1].y + w0v.z*Y[2].y + w0v.w*Y[3].y;
            acc[o].z += w2v.x*X[0].z + w2v.y*X[1].z + w2v.z*X[2].z + w2v.w*X[3].z
                      + w0v.x*Y[0].z + w0v.y*Y[1].z + w0v.z*Y[2].z + w0v.w*Y[3].z;
            acc[o].w += w2v.x*X[0].w + w2v.y*X[1].w + w2v.z*X[2].w + w2v.w*X[3].w
                      + w0v.x*Y[0].w + w0v.y*Y[1].w + w0v.z*Y[2].w + w0v.w*Y[3].w;
        }
    }
    #pragma unroll
    for (int o=0;o<16;o++) ou4[(size_t)(og*16+o)*N4+base]=acc[o];
}

// ---------------- final: out = gelu(W[64,192] @ [o1;o2;o3] + b) ----------------
__global__ __launch_bounds__(256,2)
void finalf_k(const float* __restrict__ o1, const float* __restrict__ o2,
              const float* __restrict__ o3, const float* __restrict__ w,
              const float* __restrict__ bias, float* __restrict__ out){
    extern __shared__ float4 wsf[];       // 64*48 float4
    __shared__ float bs[CC];
    for (int i=threadIdx.x;i<CC*48;i+=256) wsf[i]=((const float4*)w)[i];
    if (threadIdx.x<CC) bs[threadIdx.x]=bias[threadIdx.x];
    __syncthreads();
    int og  = threadIdx.x>>6;
    int base= blockIdx.x*64 + (threadIdx.x&63);
    float4 acc[16];
    #pragma unroll
    for (int o=0;o<16;o++){ float bv=bs[og*16+o]; acc[o]=make_float4(bv,bv,bv,bv); }
    const float* srcs[3]={o1,o2,o3};
    #pragma unroll 1
    for (int part=0;part<3;part++){
        const float4* in4 = (const float4*)(srcs[part] + (size_t)blockIdx.y*CC*NN);
        #pragma unroll 1
        for (int c=0;c<CC;c+=4){
            float4 X[4];
            #pragma unroll
            for (int u=0;u<4;u++) X[u]=in4[(size_t)(c+u)*N4+base];
            #pragma unroll
            for (int o=0;o<16;o++){
                float4 wv = wsf[(og*16+o)*48 + part*16 + (c>>2)];
                acc[o].x += wv.x*X[0].x + wv.y*X[1].x + wv.z*X[2].x + wv.w*X[3].x;
                acc[o].y += wv.x*X[0].y + wv.y*X[1].y + wv.z*X[2].y + wv.w*X[3].y;
                acc[o].z += wv.x*X[0].z + wv.y*X[1].z + wv.z*X[2].z + wv.w*X[3].z;
                acc[o].w += wv.x*X[0].w + wv.y*X[1].w + wv.z*X[2].w + wv.w*X[3].w;
            }
        }
    }
    float4* ou4 = (float4*)(out + (size_t)blockIdx.y*CC*NN);
    #pragma unroll
    for (int o=0;o<16;o++){
        float4 r=acc[o];
        r.x=gelu_f(r.x); r.y=gelu_f(r.y); r.z=gelu_f(r.z); r.w=gelu_f(r.w);
        ou4[(size_t)(og*16+o)*N4+base]=r;
    }
}

// ---------------- depthwise 3x3 + bias + gelu ----------------
__global__ void dwconv_k(const float* __restrict__ in, const float* __restrict__ w,
                         const float* __restrict__ bias, float* __restrict__ out){
    int idx = blockIdx.x*blockDim.x + threadIdx.x;
    if (idx >= BB*CC*NN) return;
    int n = idx % NN; int bc = idx / NN; int c = bc % CC;
    int y = n / WW, x = n % WW;
    const float* wp = w + c*9;
    const float* ip = in + (size_t)bc*NN;
    float acc = bias[c];
    #pragma unroll
    for (int ky=0;ky<3;ky++){
        int yy = y+ky-1; if (yy<0||yy>=HH) continue;
        #pragma unroll
        for (int kx=0;kx<3;kx++){
            int xx = x+kx-1; if (xx<0||xx>=WW) continue;
            acc += wp[ky*3+kx]*ip[(size_t)yy*WW+xx];
        }
    }
    out[idx] = gelu_f(acc);
}

// ---------------- transpose [b,c,H,W] -> [b,c,W,H] ----------------
__global__ void transpose_k(const float* __restrict__ in, float* __restrict__ out){
    __shared__ float t[32][33];
    const float* ib = in + (size_t)blockIdx.z*NN;
    float* ob = out + (size_t)blockIdx.z*NN;
    int x = blockIdx.x*32 + threadIdx.x;
    #pragma unroll
    for (int k=0;k<32;k+=8)
        t[threadIdx.y+k][threadIdx.x] = ib[(size_t)(blockIdx.y*32+threadIdx.y+k)*WW + x];
    __syncthreads();
    int x2 = blockIdx.y*32 + threadIdx.x;
    #pragma unroll
    for (int k=0;k<32;k+=8)
        ob[(size_t)(blockIdx.x*32+threadIdx.y+k)*HH + x2] = t[threadIdx.x][threadIdx.y+k];
}

// ---------------- row-wise sum of squares for q,k ----------------
__global__ void norm_k(const float* __restrict__ q, const float* __restrict__ k){
    int id = blockIdx.x;
    const float* src = (id < BB*CC) ? q : k;
    int bc = id % (BB*CC);
    const float* r = src + (size_t)bc*NN;
    float s=0.f;
    for (int n=threadIdx.x;n<NN;n+=256){ float v=r[n]; s+=v*v; }
    __shared__ float red[256];
    red[threadIdx.x]=s; __syncthreads();
    for (int o=128;o;o>>=1){ if(threadIdx.x<o) red[threadIdx.x]+=red[threadIdx.x+o]; __syncthreads(); }
    if (threadIdx.x==0) g_norm[id]=red[0];
}

__global__ void zero_attn_k(){
    int i = blockIdx.x*blockDim.x+threadIdx.x;
    if (i < BB*NHEADS*32*32) g_attn[i]=0.f;
}

// ---------------- channel-attn gram (chunked atomics) ----------------
#define NCHUNK 32
#define CHUNK (NN/NCHUNK)
__global__ void gram_k(const float* __restrict__ q, const float* __restrict__ k){
    int bg = blockIdx.x; int b=bg/NHEADS, g=bg%NHEADS;
    int n0 = blockIdx.y*CHUNK;
    __shared__ float qs[64][33], ks[64][33];
    int c = threadIdx.x>>3, dg = threadIdx.x&7;
    float a0=0,a1=0,a2=0,a3=0;
    const float* qb = q + ((size_t)(b*CC + g*32))*NN + n0;
    const float* kb = k + ((size_t)(b*CC + g*32))*NN + n0;
    for (int tt=0;tt<CHUNK;tt+=64){
        __syncthreads();
        for (int e=threadIdx.x;e<32*64;e+=256){
            int cc=e>>6, t=e&63;
            qs[t][cc]=qb[(size_t)cc*NN + tt + t];
            ks[t][cc]=kb[(size_t)cc*NN + tt + t];
        }
        __syncthreads();
        #pragma unroll 8
        for (int t=0;t<64;t++){
            float qv=qs[t][c];
            a0+=qv*ks[t][dg];    a1+=qv*ks[t][dg+8];
            a2+=qv*ks[t][dg+16]; a3+=qv*ks[t][dg+24];
        }
    }
    float* ab = g_attn + ((size_t)(bg*32+c))*32;
    atomicAdd(&ab[dg],a0);    atomicAdd(&ab[dg+8],a1);
    atomicAdd(&ab[dg+16],a2); atomicAdd(&ab[dg+24],a3);
}

// ---------------- channel-attn softmax ----------------
__global__ void chsm_k(const float* __restrict__ temp){
    int bg = blockIdx.x; int b=bg/NHEADS, g=bg%NHEADS;
    int c = threadIdx.x>>5, d = threadIdx.x&31;
    float nq = fmaxf(sqrtf(g_norm[b*CC + g*32 + c]), 1e-12f);
    float nk = fmaxf(sqrtf(g_norm[BB*CC + b*CC + g*32 + d]), 1e-12f);
    int idx = (bg*32+c)*32+d;
    float v = g_attn[idx]/(nq*nk)*temp[g];
    float m=v;
    #pragma unroll
    for (int o=16;o;o>>=1) m=fmaxf(m,__shfl_xor_sync(0xffffffffu,m,o));
    float e=expf(v-m), s=e;
    #pragma unroll
    for (int o=16;o;o>>=1) s+=__shfl_xor_sync(0xffffffffu,s,o);
    g_attn[idx]=e/s;
}

// ---------------- mid = attn @ v ----------------
__global__ void attnv_k(const float* __restrict__ v, float* __restrict__ mid){
    __shared__ float4 as4[NHEADS*32*8];
    int b = blockIdx.y;
    int n = blockIdx.x*256 + threadIdx.x;
    const float4* ag = (const float4*)(g_attn + b*NHEADS*32*32);
    for (int i=threadIdx.x;i<NHEADS*32*8;i+=256) as4[i]=ag[i];
    __syncthreads();
    const float* vb = v + (size_t)b*CC*NN + n;
    float* mb = mid + (size_t)b*CC*NN + n;
    #pragma unroll
    for (int g=0;g<NHEADS;g++){
        float vv[32];
        #pragma unroll
        for (int d=0;d<32;d++) vv[d]=vb[(size_t)(g*32+d)*NN];
        #pragma unroll 1
        for (int c=0;c<32;c++){
            float a=0.f;
            #pragma unroll
            for (int d4=0;d4<8;d4++){
                float4 av=as4[(g*32+c)*8+d4];
                a += av.x*vv[d4*4]+av.y*vv[d4*4+1]+av.z*vv[d4*4+2]+av.w*vv[d4*4+3];
            }
            mb[(size_t)(g*32+c)*NN]=a;
        }
    }
}

// ---------------- gram: s[blk,i,j] = sum_c Q[b,c,r,i] K[b,c,r,j], blk=(b,r) ----------------
__global__ void rowgram_k(const float* __restrict__ Q, const float* __restrict__ K,
                          float* __restrict__ s){
    int b = blockIdx.x/HH, h = blockIdx.x%HH;
    __shared__ float qs[CC][WW];    // 48KB
    const float* qb = Q + (size_t)b*CC*NN + (size_t)h*WW;
    for (int e=threadIdx.x;e<CC*WW;e+=192){ int c=e/WW, i=e%WW; qs[c][i]=qb[(size_t)c*NN+i]; }
    int j = threadIdx.x;
    float kr[CC];
    const float* kb = K + (size_t)b*CC*NN + (size_t)h*WW + j;
    #pragma unroll
    for (int c=0;c<CC;c++) kr[c]=kb[(size_t)c*NN];
    __syncthreads();
    float* sb = s + (size_t)blockIdx.x*WW*WW + j;
    #pragma unroll 1
    for (int i=0;i<WW;i+=4){
        float a0=0,a1=0,a2=0,a3=0;
        #pragma unroll
        for (int c=0;c<CC;c++){
            float4 qv=*(const float4*)&qs[c][i];
            float kv=kr[c];
            a0+=qv.x*kv; a1+=qv.y*kv; a2+=qv.z*kv; a3+=qv.w*kv;
        }
        sb[(size_t)(i+0)*WW]=a0; sb[(size_t)(i+1)*WW]=a1;
        sb[(size_t)(i+2)*WW]=a2; sb[(size_t)(i+3)*WW]=a3;
    }
}

// -------- out[b,c,r,i] = gamma*sum_j V[b,c,r,j]*softmax_j(s[blk,i,:]) + res, fused softmax --------
#define VSP 196
__global__ __launch_bounds__(192,2)
void rowout_k(const float* __restrict__ V, const float* __restrict__ s,
              const float* __restrict__ res, const float* __restrict__ gamma_p,
              float* __restrict__ out){
    extern __shared__ float sm[];
    float* vs   = sm;                    // [64][VSP]
    float* as   = vs + CC*VSP;           // [192][36]
    float* rowm = as + 192*36;
    float* rowi = rowm + 192;
    int b = blockIdx.x/HH, h = blockIdx.x%HH;
    const float* vb = V + (size_t)b*CC*NN + (size_t)h*WW;
    for (int e=threadIdx.x;e<CC*WW;e+=192){ int c=e/WW, j=e%WW; vs[c*VSP+j]=vb[(size_t)c*NN+j]; }
    int i = threadIdx.x;
    const float* sblk = s + (size_t)blockIdx.x*WW*WW;
    // online softmax stats for row i
    {
        const float4* sr4 = (const float4*)(sblk + (size_t)i*WW);
        float m=-3.4e38f, sum=0.f;
        #pragma unroll 4
        for (int u=0;u<WW/4;u++){
            float4 t=sr4[u];
            float lm = fmaxf(fmaxf(t.x,t.y),fmaxf(t.z,t.w));
            float nm = fmaxf(m,lm);
            sum = sum*expf(m-nm) + expf(t.x-nm)+expf(t.y-nm)+expf(t.z-nm)+expf(t.w-nm);
            m = nm;
        }
        rowm[i]=m; rowi[i]=1.f/sum;
    }
    float acc[CC];
    #pragma unroll
    for (int c=0;c<CC;c++) acc[c]=0.f;
    for (int j0=0;j0<WW;j0+=32){
        __syncthreads();
        for (int e=threadIdx.x;e<192*32;e+=192){
            int ii=e>>5, jt=e&31;
            float v = sblk[(size_t)ii*WW + j0+jt];
            as[ii*36+jt] = expf(v - rowm[ii])*rowi[ii];
        }
        __syncthreads();
        #pragma unroll
        for (int jt=0;jt<32;jt+=4){
            float4 av = *(const float4*)&as[i*36+jt];
            #pragma unroll
            for (int c=0;c<CC;c++){
                float4 vv = *(const float4*)&vs[c*VSP + j0+jt];
                acc[c] += vv.x*av.x + vv.y*av.y + vv.z*av.z + vv.w*av.w;
            }
        }
    }
    float gm = gamma_p[0];
    const float* rb = res + (size_t)b*CC*NN + (size_t)h*WW + i;
    float* ob = out + (size_t)b*CC*NN + (size_t)h*WW + i;
    #pragma unroll
    for (int c=0;c<CC;c++) ob[(size_t)c*NN] = gm*acc[c] + rb[(size_t)c*NN];
}

// =======================================================================
extern "C" void kernel_launch(void* const* d_in, const int* in_sizes, int n_in,
                              void* d_out, int out_size){
    const float* x      =(const float*)d_in[0];
    const float* pw_w   =(const float*)d_in[1];
    const float* dw_w   =(const float*)d_in[2];
    const float* dw_b   =(const float*)d_in[3];
    const float* conv2_w=(const float*)d_in[4];
    const float* conv2_b=(const float*)d_in[5];
    const float* conv0_w=(const float*)d_in[6];
    const float* conv0_b=(const float*)d_in[7];
    const float* att_q_w=(const float*)d_in[8];
    const float* att_k_w=(const float*)d_in[9];
    const float* att_v_w=(const float*)d_in[10];
    const float* att_p_w=(const float*)d_in[11];
    const float* temp   =(const float*)d_in[12];
    const float* row_q_w=(const float*)d_in[13];
    const float* row_k_w=(const float*)d_in[14];
    const float* row_v_w=(const float*)d_in[15];
    const float* row_g  =(const float*)d_in[16];
    const float* col_q_w=(const float*)d_in[17];
    const float* col_k_w=(const float*)d_in[18];
    const float* col_v_w=(const float*)d_in[19];
    const float* col_g  =(const float*)d_in[20];
    const float* conv_w =(const float*)d_in[21];
    const float* conv_b =(const float*)d_in[22];
    float* out=(float*)d_out;

    float *t0,*t1,*x1b,*q,*k,*v,*o1,*o2,*o3,*s;
    cudaGetSymbolAddress((void**)&t0,  g_t0);
    cudaGetSymbolAddress((void**)&t1,  g_t1);
    cudaGetSymbolAddress((void**)&x1b, g_x1);
    cudaGetSymbolAddress((void**)&q,   g_q);
    cudaGetSymbolAddress((void**)&k,   g_k);
    cudaGetSymbolAddress((void**)&v,   g_v);
    cudaGetSymbolAddress((void**)&o1,  g_o1);
    cudaGetSymbolAddress((void**)&o2,  g_o2);
    cudaGetSymbolAddress((void**)&o3,  g_o3);
    cudaGetSymbolAddress((void**)&s,   g_s);

    const int SM_ROWOUT = (CC*VSP + 192*36 + 2*192)*4;   // 79360 B
    const int SM_FINAL  = CC*48*16;                      // 49152 B
    static bool attr_done=false;
    if(!attr_done){
        cudaFuncSetAttribute(rowout_k, cudaFuncAttributeMaxDynamicSharedMemorySize, SM_ROWOUT);
        cudaFuncSetAttribute(finalf_k, cudaFuncAttributeMaxDynamicSharedMemorySize, SM_FINAL);
        attr_done=true;
    }

    dim3 cg(NN/256, BB);

    // ---- BSConvU + skip -> x1 ----
    zero_attn_k<<<32,256>>>();
    convf_k<false><<<cg,256>>>(x, pw_w, nullptr, t0);
    dwconv_k<<<(BB*CC*NN)/256,256>>>(t0, dw_w, dw_b, t1);           // t1 = gelu(dw+bias)
    x1f_k<<<cg,256>>>(t1, x, conv2_w, conv2_b, conv0_w, conv0_b, x1b);

    // ---- channel self-attention -> o1 ----
    convf_k<false><<<cg,256>>>(x1b, att_q_w, nullptr, q);
    convf_k<false><<<cg,256>>>(x1b, att_k_w, nullptr, k);
    convf_k<false><<<cg,256>>>(x1b, att_v_w, nullptr, v);
    norm_k<<<2*BB*CC,256>>>(q,k);
    gram_k<<<dim3(BB*NHEADS,NCHUNK),256>>>(q,k);
    chsm_k<<<BB*NHEADS,1024>>>(temp);
    attnv_k<<<cg,256>>>(v, t0);
    convf_k<false><<<cg,256>>>(t0, att_p_w, nullptr, o1);

    // ---- row attention -> o2 ----
    convf_k<false><<<cg,256>>>(x1b, row_q_w, nullptr, q);
    convf_k<false><<<cg,256>>>(x1b, row_k_w, nullptr, k);
    convf_k<false><<<cg,256>>>(o1,  row_v_w, nullptr, v);
    rowgram_k<<<BB*HH,192>>>(q,k,s);
    rowout_k<<<BB*HH,192,SM_ROWOUT>>>(v,s,x1b,row_g,o2);

    // ---- col attention (via transposed tensors) -> o3 ----
    transpose_k<<<dim3(6,6,BB*CC),dim3(32,8)>>>(x1b, t1);           // t1 = x1^T
    transpose_k<<<dim3(6,6,BB*CC),dim3(32,8)>>>(o1,  t0);           // t0 = o1^T
    convf_k<false><<<cg,256>>>(t1, col_q_w, nullptr, q);
    convf_k<false><<<cg,256>>>(t1, col_k_w, nullptr, k);
    convf_k<false><<<cg,256>>>(t0, col_v_w, nullptr, v);
    rowgram_k<<<BB*WW,192>>>(q,k,s);
    rowout_k<<<BB*WW,192,SM_ROWOUT>>>(v,s,t1,col_g,q);              // q = o3^T
    transpose_k<<<dim3(6,6,BB*CC),dim3(32,8)>>>(q, o3);

    // ---- fuse ----
    finalf_k<<<cg,256,SM_FINAL>>>(o1,o2,o3,conv_w,conv_b,out);
}

// round 6
// speedup vs baseline: 1.6262x; 1.1471x over previous
#include <cuda_runtime.h>
#include <math.h>
#include <stdint.h>

#define BB 4
#define CC 64
#define HH 192
#define WW 192
#define NN (HH*WW)          // 36864
#define N4 (NN/4)
#define PP (BB*NN)
#define NHEADS 2

// ---------------- scratch ----------------
__device__ float g_t0[BB*CC*NN];
__device__ float g_t1[BB*CC*NN];
__device__ float g_x1[BB*CC*NN];
__device__ float g_q [BB*CC*NN];
__device__ float g_k [BB*CC*NN];
__device__ float g_v [BB*CC*NN];
__device__ float g_o1[BB*CC*NN];
__device__ float g_o2[BB*CC*NN];
__device__ float g_o3[BB*CC*NN];
__device__ float g_s [BB*HH*WW*WW];
__device__ float g_norm[2*BB*CC];
__device__ float g_attn[BB*NHEADS*32*32];

__device__ __forceinline__ float gelu_f(float v){
    return 0.5f*v*(1.f+erff(v*0.70710678118654752f));
}
__device__ __forceinline__ uint32_t f2tf(float f){
    uint32_t u; asm("cvt.rna.tf32.f32 %0, %1;" : "=r"(u) : "f"(f)); return u;
}
__device__ __forceinline__ void mma8(float* d, const uint32_t* a, uint32_t b0, uint32_t b1){
    asm("mma.sync.aligned.m16n8k8.row.col.f32.tf32.tf32.f32 "
        "{%0,%1,%2,%3},{%4,%5,%6,%7},{%8,%9},{%0,%1,%2,%3};"
        : "+f"(d[0]),"+f"(d[1]),"+f"(d[2]),"+f"(d[3])
        : "r"(a[0]),"r"(a[1]),"r"(a[2]),"r"(a[3]),"r"(b0),"r"(b1));
}

#define SX 136   // X smem row stride (floats)
#define SWT 68   // W smem row stride

// split-store helper: hi/lo tf32 of float4 into smem
__device__ __forceinline__ void st_split4(uint32_t* h, uint32_t* l, float4 v){
    uint32_t hx=f2tf(v.x), hy=f2tf(v.y), hz=f2tf(v.z), hw=f2tf(v.w);
    h[0]=hx; h[1]=hy; h[2]=hz; h[3]=hw;
    l[0]=f2tf(v.x-__uint_as_float(hx));
    l[1]=f2tf(v.y-__uint_as_float(hy));
    l[2]=f2tf(v.z-__uint_as_float(hz));
    l[3]=f2tf(v.w-__uint_as_float(hw));
}

// =====================================================================
// QKV-style mma conv: NS weight sets sharing one input. K=64.
// Block: 64 out-ch x 128 px. grid(NN/128, BB), 256 thr.
// =====================================================================
template<int NS>
__global__ __launch_bounds__(256, NS==1?2:1)
void qkvmma_k(const float* __restrict__ in,
              const float* __restrict__ w0,const float* __restrict__ w1,const float* __restrict__ w2,
              float* __restrict__ p0,float* __restrict__ p1,float* __restrict__ p2){
    extern __shared__ uint32_t smu[];
    uint32_t* xh = smu;
    uint32_t* xl = xh + CC*SX;
    uint32_t* wh = xl + CC*SX;
    uint32_t* wl = wh + NS*CC*SWT;
    int tid=threadIdx.x, wid=tid>>5, lane=tid&31;
    const float* wptr[3]={w0,w1,w2};
    float* optr[3]={p0,p1,p2};
    size_t bbase=(size_t)blockIdx.y*CC*NN;
    int nblk=blockIdx.x*128;
    const float* ib = in + bbase + nblk;
    #pragma unroll
    for (int r=0;r<8;r++){
        int row = wid*8 + r;
        float4 v = *(const float4*)(ib + (size_t)row*NN + lane*4);
        int base = row*SX + lane*4;
        st_split4(xh+base, xl+base, v);
    }
    #pragma unroll
    for (int s=0;s<NS;s++){
        const float* wp=wptr[s];
        #pragma unroll
        for (int i=0;i<4;i++){
            int idx=tid+i*256; int o=idx>>4, c4=idx&15;
            float4 v=*(const float4*)(wp + o*64 + c4*4);
            int base = s*CC*SWT + o*SWT + c4*4;
            st_split4(wh+base, wl+base, v);
        }
    }
    __syncthreads();
    int wm=wid&3, wn=wid>>2, g=lane>>2, tg=lane&3;
    float acc[NS][8][4];
    #pragma unroll
    for (int s=0;s<NS;s++)
        #pragma unroll
        for (int t=0;t<8;t++)
            #pragma unroll
            for (int e=0;e<4;e++) acc[s][t][e]=0.f;
    #pragma unroll
    for (int ks=0;ks<8;ks++){
        int k0=ks*8;
        uint32_t B0h[8],B1h[8],B0l[8],B1l[8];
        #pragma unroll
        for (int t=0;t<8;t++){
            int n0=wn*64+t*8+g;
            int i0=(k0+tg)*SX+n0, i1=(k0+4+tg)*SX+n0;
            B0h[t]=xh[i0]; B1h[t]=xh[i1];
            B0l[t]=xl[i0]; B1l[t]=xl[i1];
        }
        #pragma unroll
        for (int s=0;s<NS;s++){
            const uint32_t* whb=wh+s*CC*SWT;
            const uint32_t* wlb=wl+s*CC*SWT;
            int r0=(wm*16+g)*SWT+k0+tg, r1=(wm*16+8+g)*SWT+k0+tg;
            uint32_t Ah[4],Al[4];
            Ah[0]=whb[r0]; Ah[1]=whb[r1]; Ah[2]=whb[r0+4]; Ah[3]=whb[r1+4];
            Al[0]=wlb[r0]; Al[1]=wlb[r1]; Al[2]=wlb[r0+4]; Al[3]=wlb[r1+4];
            #pragma unroll
            for (int t=0;t<8;t++){
                mma8(acc[s][t],Ah,B0h[t],B1h[t]);
                mma8(acc[s][t],Ah,B0l[t],B1l[t]);
                mma8(acc[s][t],Al,B0h[t],B1h[t]);
            }
        }
    }
    #pragma unroll
    for (int s=0;s<NS;s++){
        float* ob = optr[s] + bbase + nblk;
        #pragma unroll
        for (int t=0;t<8;t++){
            int n0 = wn*64 + t*8 + 2*tg;
            int r0 = wm*16 + g;
            *(float2*)(ob + (size_t)r0*NN + n0)     = make_float2(acc[s][t][0],acc[s][t][1]);
            *(float2*)(ob + (size_t)(r0+8)*NN + n0) = make_float2(acc[s][t][2],acc[s][t][3]);
        }
    }
}

// =====================================================================
// K-concat mma conv: out = sum_c W_c @ in_c (+bias0[+bias1]) [gelu]
// wstride = weight row stride (64 for separate arrays, 192 for conv_w)
// =====================================================================
template<int NC,int NB,bool GELU>
__global__ __launch_bounds__(256,2)
void cmma_k(const float* __restrict__ in0,const float* __restrict__ in1,const float* __restrict__ in2,
            const float* __restrict__ w0,const float* __restrict__ w1,const float* __restrict__ w2,
            int wstride,
            const float* __restrict__ bias0,const float* __restrict__ bias1,
            float* __restrict__ outp){
    extern __shared__ uint32_t smu[];
    uint32_t* xh = smu;
    uint32_t* xl = xh + CC*SX;
    uint32_t* wh = xl + CC*SX;
    uint32_t* wl = wh + CC*SWT;
    __shared__ float bs[CC];
    int tid=threadIdx.x, wid=tid>>5, lane=tid&31;
    if (NB>0 && tid<CC){ float bv=bias0[tid]; if (NB>1) bv+=bias1[tid]; bs[tid]=bv; }
    const float* ip[3]={in0,in1,in2};
    const float* wp[3]={w0,w1,w2};
    size_t bbase=(size_t)blockIdx.y*CC*NN;
    int nblk=blockIdx.x*128;
    int wm=wid&3, wn=wid>>2, g=lane>>2, tg=lane&3;
    float acc[8][4];
    #pragma unroll
    for (int t=0;t<8;t++){ acc[t][0]=0;acc[t][1]=0;acc[t][2]=0;acc[t][3]=0; }
    #pragma unroll 1
    for (int c=0;c<NC;c++){
        if (c) __syncthreads();
        const float* ib = ip[c] + bbase + nblk;
        #pragma unroll
        for (int r=0;r<8;r++){
            int row = wid*8 + r;
            float4 v = *(const float4*)(ib + (size_t)row*NN + lane*4);
            int base = row*SX + lane*4;
            st_split4(xh+base, xl+base, v);
        }
        const float* wpc = wp[c];
        #pragma unroll
        for (int i=0;i<4;i++){
            int idx=tid+i*256; int o=idx>>4, c4=idx&15;
            float4 v=*(const float4*)(wpc + (size_t)o*wstride + c4*4);
            int base = o*SWT + c4*4;
            st_split4(wh+base, wl+base, v);
        }
        __syncthreads();
        #pragma unroll
        for (int ks=0;ks<8;ks++){
            int k0=ks*8;
            int r0=(wm*16+g)*SWT+k0+tg, r1=(wm*16+8+g)*SWT+k0+tg;
            uint32_t Ah[4],Al[4];
            Ah[0]=wh[r0]; Ah[1]=wh[r1]; Ah[2]=wh[r0+4]; Ah[3]=wh[r1+4];
            Al[0]=wl[r0]; Al[1]=wl[r1]; Al[2]=wl[r0+4]; Al[3]=wl[r1+4];
            #pragma unroll
            for (int t=0;t<8;t++){
                int n0=wn*64+t*8+g;
                int i0=(k0+tg)*SX+n0, i1=(k0+4+tg)*SX+n0;
                uint32_t b0h=xh[i0], b1h=xh[i1], b0l=xl[i0], b1l=xl[i1];
                mma8(acc[t],Ah,b0h,b1h);
                mma8(acc[t],Ah,b0l,b1l);
                mma8(acc[t],Al,b0h,b1h);
            }
        }
    }
    float* ob = outp + bbase + nblk;
    #pragma unroll
    for (int t=0;t<8;t++){
        int n0 = wn*64 + t*8 + 2*tg;
        int r0 = wm*16 + g;
        float2 v0 = make_float2(acc[t][0],acc[t][1]);
        float2 v1 = make_float2(acc[t][2],acc[t][3]);
        if (NB>0){ float b0v=bs[r0], b1v=bs[r0+8];
                   v0.x+=b0v; v0.y+=b0v; v1.x+=b1v; v1.y+=b1v; }
        if (GELU){ v0.x=gelu_f(v0.x); v0.y=gelu_f(v0.y); v1.x=gelu_f(v1.x); v1.y=gelu_f(v1.y); }
        *(float2*)(ob + (size_t)r0*NN + n0)     = v0;
        *(float2*)(ob + (size_t)(r0+8)*NN + n0) = v1;
    }
}

// ---------------- depthwise 3x3 + bias + gelu ----------------
__global__ void dwconv_k(const float* __restrict__ in, const float* __restrict__ w,
                         const float* __restrict__ bias, float* __restrict__ out){
    int idx = blockIdx.x*blockDim.x + threadIdx.x;
    if (idx >= BB*CC*NN) return;
    int n = idx % NN; int bc = idx / NN; int c = bc % CC;
    int y = n / WW, x = n % WW;
    const float* wp = w + c*9;
    const float* ip = in + (size_t)bc*NN;
    float acc = bias[c];
    #pragma unroll
    for (int ky=0;ky<3;ky++){
        int yy = y+ky-1; if (yy<0||yy>=HH) continue;
        #pragma unroll
        for (int kx=0;kx<3;kx++){
            int xx = x+kx-1; if (xx<0||xx>=WW) continue;
            acc += wp[ky*3+kx]*ip[(size_t)yy*WW+xx];
        }
    }
    out[idx] = gelu_f(acc);
}

// ---------------- transpose [b,c,H,W] -> [b,c,W,H] ----------------
__global__ void transpose_k(const float* __restrict__ in, float* __restrict__ out){
    __shared__ float t[32][33];
    const float* ib = in + (size_t)blockIdx.z*NN;
    float* ob = out + (size_t)blockIdx.z*NN;
    int x = blockIdx.x*32 + threadIdx.x;
    #pragma unroll
    for (int k=0;k<32;k+=8)
        t[threadIdx.y+k][threadIdx.x] = ib[(size_t)(blockIdx.y*32+threadIdx.y+k)*WW + x];
    __syncthreads();
    int x2 = blockIdx.y*32 + threadIdx.x;
    #pragma unroll
    for (int k=0;k<32;k+=8)
        ob[(size_t)(blockIdx.x*32+threadIdx.y+k)*HH + x2] = t[threadIdx.x][threadIdx.y+k];
}

// ---------------- q,k row sum-of-squares ----------------
__global__ void norm_k(const float* __restrict__ q, const float* __restrict__ k){
    int id = blockIdx.x;
    const float* src = (id < BB*CC) ? q : k;
    int bc = id % (BB*CC);
    const float* r = src + (size_t)bc*NN;
    float s=0.f;
    for (int n=threadIdx.x;n<NN;n+=256){ float v=r[n]; s+=v*v; }
    __shared__ float red[256];
    red[threadIdx.x]=s; __syncthreads();
    for (int o=128;o;o>>=1){ if(threadIdx.x<o) red[threadIdx.x]+=red[threadIdx.x+o]; __syncthreads(); }
    if (threadIdx.x==0) g_norm[id]=red[0];
}

__global__ void zero_attn_k(){
    int i = blockIdx.x*blockDim.x+threadIdx.x;
    if (i < BB*NHEADS*32*32) g_attn[i]=0.f;
}

// ---------------- channel-attn gram (chunked atomics) ----------------
#define NCHUNK 32
#define CHUNK (NN/NCHUNK)
__global__ void gram_k(const float* __restrict__ q, const float* __restrict__ k){
    int bg = blockIdx.x; int b=bg/NHEADS, g=bg%NHEADS;
    int n0 = blockIdx.y*CHUNK;
    __shared__ float qs[64][33], ks[64][33];
    int c = threadIdx.x>>3, dg = threadIdx.x&7;
    float a0=0,a1=0,a2=0,a3=0;
    const float* qb = q + ((size_t)(b*CC + g*32))*NN + n0;
    const float* kb = k + ((size_t)(b*CC + g*32))*NN + n0;
    for (int tt=0;tt<CHUNK;tt+=64){
        __syncthreads();
        for (int e=threadIdx.x;e<32*64;e+=256){
            int cc=e>>6, t=e&63;
            qs[t][cc]=qb[(size_t)cc*NN + tt + t];
            ks[t][cc]=kb[(size_t)cc*NN + tt + t];
        }
        __syncthreads();
        #pragma unroll 8
        for (int t=0;t<64;t++){
            float qv=qs[t][c];
            a0+=qv*ks[t][dg];    a1+=qv*ks[t][dg+8];
            a2+=qv*ks[t][dg+16]; a3+=qv*ks[t][dg+24];
        }
    }
    float* ab = g_attn + ((size_t)(bg*32+c))*32;
    atomicAdd(&ab[dg],a0);    atomicAdd(&ab[dg+8],a1);
    atomicAdd(&ab[dg+16],a2); atomicAdd(&ab[dg+24],a3);
}

// ---------------- channel-attn softmax ----------------
__global__ void chsm_k(const float* __restrict__ temp){
    int bg = blockIdx.x; int b=bg/NHEADS, g=bg%NHEADS;
    int c = threadIdx.x>>5, d = threadIdx.x&31;
    float nq = fmaxf(sqrtf(g_norm[b*CC + g*32 + c]), 1e-12f);
    float nk = fmaxf(sqrtf(g_norm[BB*CC + b*CC + g*32 + d]), 1e-12f);
    int idx = (bg*32+c)*32+d;
    float v = g_attn[idx]/(nq*nk)*temp[g];
    float m=v;
    #pragma unroll
    for (int o=16;o;o>>=1) m=fmaxf(m,__shfl_xor_sync(0xffffffffu,m,o));
    float e=expf(v-m), s=e;
    #pragma unroll
    for (int o=16;o;o>>=1) s+=__shfl_xor_sync(0xffffffffu,s,o);
    g_attn[idx]=e/s;
}

// ---------------- mid = attn @ v ----------------
__global__ void attnv_k(const float* __restrict__ v, float* __restrict__ mid){
    __shared__ float4 as4[NHEADS*32*8];
    int b = blockIdx.y;
    int n = blockIdx.x*256 + threadIdx.x;
    const float4* ag = (const float4*)(g_attn + b*NHEADS*32*32);
    for (int i=threadIdx.x;i<NHEADS*32*8;i+=256) as4[i]=ag[i];
    __syncthreads();
    const float* vb = v + (size_t)b*CC*NN + n;
    float* mb = mid + (size_t)b*CC*NN + n;
    #pragma unroll
    for (int g=0;g<NHEADS;g++){
        float vv[32];
        #pragma unroll
        for (int d=0;d<32;d++) vv[d]=vb[(size_t)(g*32+d)*NN];
        #pragma unroll 1
        for (int c=0;c<32;c++){
            float a=0.f;
            #pragma unroll
            for (int d4=0;d4<8;d4++){
                float4 av=as4[(g*32+c)*8+d4];
                a += av.x*vv[d4*4]+av.y*vv[d4*4+1]+av.z*vv[d4*4+2]+av.w*vv[d4*4+3];
            }
            mb[(size_t)(g*32+c)*NN]=a;
        }
    }
}

// ---------------- gram: s[blk,i,j] = sum_c Q[b,c,r,i] K[b,c,r,j] ----------------
__global__ void rowgram_k(const float* __restrict__ Q, const float* __restrict__ K,
                          float* __restrict__ s){
    int b = blockIdx.x/HH, h = blockIdx.x%HH;
    __shared__ float qs[CC][WW];
    const float* qb = Q + (size_t)b*CC*NN + (size_t)h*WW;
    for (int e=threadIdx.x;e<CC*WW;e+=192){ int c=e/WW, i=e%WW; qs[c][i]=qb[(size_t)c*NN+i]; }
    int j = threadIdx.x;
    float kr[CC];
    const float* kb = K + (size_t)b*CC*NN + (size_t)h*WW + j;
    #pragma unroll
    for (int c=0;c<CC;c++) kr[c]=kb[(size_t)c*NN];
    __syncthreads();
    float* sb = s + (size_t)blockIdx.x*WW*WW + j;
    #pragma unroll 1
    for (int i=0;i<WW;i+=4){
        float a0=0,a1=0,a2=0,a3=0;
        #pragma unroll
        for (int c=0;c<CC;c++){
            float4 qv=*(const float4*)&qs[c][i];
            float kv=kr[c];
            a0+=qv.x*kv; a1+=qv.y*kv; a2+=qv.z*kv; a3+=qv.w*kv;
        }
        sb[(size_t)(i+0)*WW]=a0; sb[(size_t)(i+1)*WW]=a1;
        sb[(size_t)(i+2)*WW]=a2; sb[(size_t)(i+3)*WW]=a3;
    }
}

// -------- fused-softmax attention apply + residual --------
#define VSP 196
__global__ __launch_bounds__(192,2)
void rowout_k(const float* __restrict__ V, const float* __restrict__ s,
              const float* __restrict__ res, const float* __restrict__ gamma_p,
              float* __restrict__ out){
    extern __shared__ float sm[];
    float* vs   = sm;
    float* as   = vs + CC*VSP;
    float* rowm = as + 192*36;
    float* rowi = rowm + 192;
    int b = blockIdx.x/HH, h = blockIdx.x%HH;
    const float* vb = V + (size_t)b*CC*NN + (size_t)h*WW;
    for (int e=threadIdx.x;e<CC*WW;e+=192){ int c=e/WW, j=e%WW; vs[c*VSP+j]=vb[(size_t)c*NN+j]; }
    int i = threadIdx.x;
    const float* sblk = s + (size_t)blockIdx.x*WW*WW;
    {
        const float4* sr4 = (const float4*)(sblk + (size_t)i*WW);
        float m=-3.4e38f, sum=0.f;
        #pragma unroll 4
        for (int u=0;u<WW/4;u++){
            float4 t=sr4[u];
            float lm = fmaxf(fmaxf(t.x,t.y),fmaxf(t.z,t.w));
            float nm = fmaxf(m,lm);
            sum = sum*expf(m-nm) + expf(t.x-nm)+expf(t.y-nm)+expf(t.z-nm)+expf(t.w-nm);
            m = nm;
        }
        rowm[i]=m; rowi[i]=1.f/sum;
    }
    float acc[CC];
    #pragma unroll
    for (int c=0;c<CC;c++) acc[c]=0.f;
    for (int j0=0;j0<WW;j0+=32){
        __syncthreads();
        for (int e=threadIdx.x;e<192*32;e+=192){
            int ii=e>>5, jt=e&31;
            float v = sblk[(size_t)ii*WW + j0+jt];
            as[ii*36+jt] = expf(v - rowm[ii])*rowi[ii];
        }
        __syncthreads();
        #pragma unroll
        for (int jt=0;jt<32;jt+=4){
            float4 av = *(const float4*)&as[i*36+jt];
            #pragma unroll
            for (int c=0;c<CC;c++){
                float4 vv = *(const float4*)&vs[c*VSP + j0+jt];
                acc[c] += vv.x*av.x + vv.y*av.y + vv.z*av.z + vv.w*av.w;
            }
        }
    }
    float gm = gamma_p[0];
    const float* rb = res + (size_t)b*CC*NN + (size_t)h*WW + i;
    float* ob = out + (size_t)b*CC*NN + (size_t)h*WW + i;
    #pragma unroll
    for (int c=0;c<CC;c++) ob[(size_t)c*NN] = gm*acc[c] + rb[(size_t)c*NN];
}

// =======================================================================
extern "C" void kernel_launch(void* const* d_in, const int* in_sizes, int n_in,
                              void* d_out, int out_size){
    const float* x      =(const float*)d_in[0];
    const float* pw_w   =(const float*)d_in[1];
    const float* dw_w   =(const float*)d_in[2];
    const float* dw_b   =(const float*)d_in[3];
    const float* conv2_w=(const float*)d_in[4];
    const float* conv2_b=(const float*)d_in[5];
    const float* conv0_w=(const float*)d_in[6];
    const float* conv0_b=(const float*)d_in[7];
    const float* att_q_w=(const float*)d_in[8];
    const float* att_k_w=(const float*)d_in[9];
    const float* att_v_w=(const float*)d_in[10];
    const float* att_p_w=(const float*)d_in[11];
    const float* temp   =(const float*)d_in[12];
    const float* row_q_w=(const float*)d_in[13];
    const float* row_k_w=(const float*)d_in[14];
    const float* row_v_w=(const float*)d_in[15];
    const float* row_g  =(const float*)d_in[16];
    const float* col_q_w=(const float*)d_in[17];
    const float* col_k_w=(const float*)d_in[18];
    const float* col_v_w=(const float*)d_in[19];
    const float* col_g  =(const float*)d_in[20];
    const float* conv_w =(const float*)d_in[21];
    const float* conv_b =(const float*)d_in[22];
    float* out=(float*)d_out;

    float *t0,*t1,*x1b,*q,*k,*v,*o1,*o2,*o3,*s;
    cudaGetSymbolAddress((void**)&t0,  g_t0);
    cudaGetSymbolAddress((void**)&t1,  g_t1);
    cudaGetSymbolAddress((void**)&x1b, g_x1);
    cudaGetSymbolAddress((void**)&q,   g_q);
    cudaGetSymbolAddress((void**)&k,   g_k);
    cudaGetSymbolAddress((void**)&v,   g_v);
    cudaGetSymbolAddress((void**)&o1,  g_o1);
    cudaGetSymbolAddress((void**)&o2,  g_o2);
    cudaGetSymbolAddress((void**)&o3,  g_o3);
    cudaGetSymbolAddress((void**)&s,   g_s);

    const int SM_Q1 = (2*CC*SX + 1*2*CC*SWT)*4;   // 104448
    const int SM_Q2 = (2*CC*SX + 2*2*CC*SWT)*4;   // 139264
    const int SM_Q3 = (2*CC*SX + 3*2*CC*SWT)*4;   // 174080
    const int SM_CM = (2*CC*SX + 2*CC*SWT)*4;     // 104448
    const int SM_ROWOUT = (CC*VSP + 192*36 + 2*192)*4;
    cudaFuncSetAttribute(qkvmma_k<1>, cudaFuncAttributeMaxDynamicSharedMemorySize, SM_Q1);
    cudaFuncSetAttribute(qkvmma_k<2>, cudaFuncAttributeMaxDynamicSharedMemorySize, SM_Q2);
    cudaFuncSetAttribute(qkvmma_k<3>, cudaFuncAttributeMaxDynamicSharedMemorySize, SM_Q3);
    cudaFuncSetAttribute(cmma_k<2,2,false>, cudaFuncAttributeMaxDynamicSharedMemorySize, SM_CM);
    cudaFuncSetAttribute(cmma_k<3,1,true>,  cudaFuncAttributeMaxDynamicSharedMemorySize, SM_CM);
    cudaFuncSetAttribute(rowout_k, cudaFuncAttributeMaxDynamicSharedMemorySize, SM_ROWOUT);

    dim3 mg(NN/128, BB);
    dim3 cg(NN/256, BB);

    // ---- BSConvU + skip -> x1 ----
    zero_attn_k<<<32,256>>>();
    qkvmma_k<1><<<mg,256,SM_Q1>>>(x, pw_w,nullptr,nullptr, t0,nullptr,nullptr);
    dwconv_k<<<(BB*CC*NN)/256,256>>>(t0, dw_w, dw_b, t1);
    cmma_k<2,2,false><<<mg,256,SM_CM>>>(t1,x,nullptr, conv2_w,conv0_w,nullptr, 64,
                                        conv2_b,conv0_b, x1b);

    // ---- channel self-attention -> o1 ----
    qkvmma_k<3><<<mg,256,SM_Q3>>>(x1b, att_q_w,att_k_w,att_v_w, q,k,v);
    norm_k<<<2*BB*CC,256>>>(q,k);
    gram_k<<<dim3(BB*NHEADS,NCHUNK),256>>>(q,k);
    chsm_k<<<BB*NHEADS,1024>>>(temp);
    attnv_k<<<cg,256>>>(v, t0);
    qkvmma_k<1><<<mg,256,SM_Q1>>>(t0, att_p_w,nullptr,nullptr, o1,nullptr,nullptr);

    // ---- row attention -> o2 ----
    qkvmma_k<2><<<mg,256,SM_Q2>>>(x1b, row_q_w,row_k_w,nullptr, q,k,nullptr);
    qkvmma_k<1><<<mg,256,SM_Q1>>>(o1, row_v_w,nullptr,nullptr, v,nullptr,nullptr);
    rowgram_k<<<BB*HH,192>>>(q,k,s);
    rowout_k<<<BB*HH,192,SM_ROWOUT>>>(v,s,x1b,row_g,o2);

    // ---- col attention (transposed) -> o3 ----
    transpose_k<<<dim3(6,6,BB*CC),dim3(32,8)>>>(x1b, t1);
    transpose_k<<<dim3(6,6,BB*CC),dim3(32,8)>>>(o1,  t0);
    qkvmma_k<2><<<mg,256,SM_Q2>>>(t1, col_q_w,col_k_w,nullptr, q,k,nullptr);
    qkvmma_k<1><<<mg,256,SM_Q1>>>(t0, col_v_w,nullptr,nullptr, v,nullptr,nullptr);
    rowgram_k<<<BB*WW,192>>>(q,k,s);
    rowout_k<<<BB*WW,192,SM_ROWOUT>>>(v,s,t1,col_g,q);
    transpose_k<<<dim3(6,6,BB*CC),dim3(32,8)>>>(q, o3);

    // ---- fuse ----
    cmma_k<3,1,true><<<mg,256,SM_CM>>>(o1,o2,o3, conv_w,conv_w+64,conv_w+128, 192,
                                       conv_b,nullptr, out);
}

// round 7
// speedup vs baseline: 2.0762x; 1.2767x over previous
#include <cuda_runtime.h>
#include <math.h>
#include <stdint.h>

#define BB 4
#define CC 64
#define HH 192
#define WW 192
#define NN (HH*WW)          // 36864
#define PP (BB*NN)
#define NHEADS 2

// ---------------- scratch ----------------
__device__ float g_t0[BB*CC*NN];
__device__ float g_t1[BB*CC*NN];
__device__ float g_x1[BB*CC*NN];
__device__ float g_q [BB*CC*NN];
__device__ float g_k [BB*CC*NN];
__device__ float g_v [BB*CC*NN];
__device__ float g_o1[BB*CC*NN];
__device__ float g_o2[BB*CC*NN];
__device__ float g_o3[BB*CC*NN];
__device__ float g_norm[2*BB*CC];
__device__ float g_attn[BB*NHEADS*32*32];

__device__ __forceinline__ float gelu_f(float v){
    return 0.5f*v*(1.f+erff(v*0.70710678118654752f));
}
__device__ __forceinline__ uint32_t f2tf(float f){
    uint32_t u; asm("cvt.rna.tf32.f32 %0, %1;" : "=r"(u) : "f"(f)); return u;
}
__device__ __forceinline__ void mma8(float* d, const uint32_t* a, uint32_t b0, uint32_t b1){
    asm("mma.sync.aligned.m16n8k8.row.col.f32.tf32.tf32.f32 "
        "{%0,%1,%2,%3},{%4,%5,%6,%7},{%8,%9},{%0,%1,%2,%3};"
        : "+f"(d[0]),"+f"(d[1]),"+f"(d[2]),"+f"(d[3])
        : "r"(a[0]),"r"(a[1]),"r"(a[2]),"r"(a[3]),"r"(b0),"r"(b1));
}

#define SX 136   // conv X smem row stride
#define SWT 68   // conv W smem row stride

__device__ __forceinline__ void st_split4(uint32_t* h, uint32_t* l, float4 v){
    uint32_t hx=f2tf(v.x), hy=f2tf(v.y), hz=f2tf(v.z), hw=f2tf(v.w);
    h[0]=hx; h[1]=hy; h[2]=hz; h[3]=hw;
    l[0]=f2tf(v.x-__uint_as_float(hx));
    l[1]=f2tf(v.y-__uint_as_float(hy));
    l[2]=f2tf(v.z-__uint_as_float(hz));
    l[3]=f2tf(v.w-__uint_as_float(hw));
}

// =====================================================================
// QKV-style mma conv: NS weight sets sharing one input. K=64.
// =====================================================================
template<int NS>
__global__ __launch_bounds__(256, NS==1?2:1)
void qkvmma_k(const float* __restrict__ in,
              const float* __restrict__ w0,const float* __restrict__ w1,const float* __restrict__ w2,
              float* __restrict__ p0,float* __restrict__ p1,float* __restrict__ p2){
    extern __shared__ uint32_t smu[];
    uint32_t* xh = smu;
    uint32_t* xl = xh + CC*SX;
    uint32_t* wh = xl + CC*SX;
    uint32_t* wl = wh + NS*CC*SWT;
    int tid=threadIdx.x, wid=tid>>5, lane=tid&31;
    const float* wptr[3]={w0,w1,w2};
    float* optr[3]={p0,p1,p2};
    size_t bbase=(size_t)blockIdx.y*CC*NN;
    int nblk=blockIdx.x*128;
    const float* ib = in + bbase + nblk;
    #pragma unroll
    for (int r=0;r<8;r++){
        int row = wid*8 + r;
        float4 v = *(const float4*)(ib + (size_t)row*NN + lane*4);
        int base = row*SX + lane*4;
        st_split4(xh+base, xl+base, v);
    }
    #pragma unroll
    for (int s=0;s<NS;s++){
        const float* wp=wptr[s];
        #pragma unroll
        for (int i=0;i<4;i++){
            int idx=tid+i*256; int o=idx>>4, c4=idx&15;
            float4 v=*(const float4*)(wp + o*64 + c4*4);
            int base = s*CC*SWT + o*SWT + c4*4;
            st_split4(wh+base, wl+base, v);
        }
    }
    __syncthreads();
    int wm=wid&3, wn=wid>>2, g=lane>>2, tg=lane&3;
    float acc[NS][8][4];
    #pragma unroll
    for (int s=0;s<NS;s++)
        #pragma unroll
        for (int t=0;t<8;t++)
            #pragma unroll
            for (int e=0;e<4;e++) acc[s][t][e]=0.f;
    #pragma unroll
    for (int ks=0;ks<8;ks++){
        int k0=ks*8;
        uint32_t B0h[8],B1h[8],B0l[8],B1l[8];
        #pragma unroll
        for (int t=0;t<8;t++){
            int n0=wn*64+t*8+g;
            int i0=(k0+tg)*SX+n0, i1=(k0+4+tg)*SX+n0;
            B0h[t]=xh[i0]; B1h[t]=xh[i1];
            B0l[t]=xl[i0]; B1l[t]=xl[i1];
        }
        #pragma unroll
        for (int s=0;s<NS;s++){
            const uint32_t* whb=wh+s*CC*SWT;
            const uint32_t* wlb=wl+s*CC*SWT;
            int r0=(wm*16+g)*SWT+k0+tg, r1=(wm*16+8+g)*SWT+k0+tg;
            uint32_t Ah[4],Al[4];
            Ah[0]=whb[r0]; Ah[1]=whb[r1]; Ah[2]=whb[r0+4]; Ah[3]=whb[r1+4];
            Al[0]=wlb[r0]; Al[1]=wlb[r1]; Al[2]=wlb[r0+4]; Al[3]=wlb[r1+4];
            #pragma unroll
            for (int t=0;t<8;t++){
                mma8(acc[s][t],Ah,B0h[t],B1h[t]);
                mma8(acc[s][t],Ah,B0l[t],B1l[t]);
                mma8(acc[s][t],Al,B0h[t],B1h[t]);
            }
        }
    }
    #pragma unroll
    for (int s=0;s<NS;s++){
        float* ob = optr[s] + bbase + nblk;
        #pragma unroll
        for (int t=0;t<8;t++){
            int n0 = wn*64 + t*8 + 2*tg;
            int r0 = wm*16 + g;
            *(float2*)(ob + (size_t)r0*NN + n0)     = make_float2(acc[s][t][0],acc[s][t][1]);
            *(float2*)(ob + (size_t)(r0+8)*NN + n0) = make_float2(acc[s][t][2],acc[s][t][3]);
        }
    }
}

// =====================================================================
// K-concat mma conv
// =====================================================================
template<int NC,int NB,bool GELU>
__global__ __launch_bounds__(256,2)
void cmma_k(const float* __restrict__ in0,const float* __restrict__ in1,const float* __restrict__ in2,
            const float* __restrict__ w0,const float* __restrict__ w1,const float* __restrict__ w2,
            int wstride,
            const float* __restrict__ bias0,const float* __restrict__ bias1,
            float* __restrict__ outp){
    extern __shared__ uint32_t smu[];
    uint32_t* xh = smu;
    uint32_t* xl = xh + CC*SX;
    uint32_t* wh = xl + CC*SX;
    uint32_t* wl = wh + CC*SWT;
    __shared__ float bs[CC];
    int tid=threadIdx.x, wid=tid>>5, lane=tid&31;
    if (NB>0 && tid<CC){ float bv=bias0[tid]; if (NB>1) bv+=bias1[tid]; bs[tid]=bv; }
    const float* ip[3]={in0,in1,in2};
    const float* wp[3]={w0,w1,w2};
    size_t bbase=(size_t)blockIdx.y*CC*NN;
    int nblk=blockIdx.x*128;
    int wm=wid&3, wn=wid>>2, g=lane>>2, tg=lane&3;
    float acc[8][4];
    #pragma unroll
    for (int t=0;t<8;t++){ acc[t][0]=0;acc[t][1]=0;acc[t][2]=0;acc[t][3]=0; }
    #pragma unroll 1
    for (int c=0;c<NC;c++){
        if (c) __syncthreads();
        const float* ib = ip[c] + bbase + nblk;
        #pragma unroll
        for (int r=0;r<8;r++){
            int row = wid*8 + r;
            float4 v = *(const float4*)(ib + (size_t)row*NN + lane*4);
            int base = row*SX + lane*4;
            st_split4(xh+base, xl+base, v);
        }
        const float* wpc = wp[c];
        #pragma unroll
        for (int i=0;i<4;i++){
            int idx=tid+i*256; int o=idx>>4, c4=idx&15;
            float4 v=*(const float4*)(wpc + (size_t)o*wstride + c4*4);
            int base = o*SWT + c4*4;
            st_split4(wh+base, wl+base, v);
        }
        __syncthreads();
        #pragma unroll
        for (int ks=0;ks<8;ks++){
            int k0=ks*8;
            int r0=(wm*16+g)*SWT+k0+tg, r1=(wm*16+8+g)*SWT+k0+tg;
            uint32_t Ah[4],Al[4];
            Ah[0]=wh[r0]; Ah[1]=wh[r1]; Ah[2]=wh[r0+4]; Ah[3]=wh[r1+4];
            Al[0]=wl[r0]; Al[1]=wl[r1]; Al[2]=wl[r0+4]; Al[3]=wl[r1+4];
            #pragma unroll
            for (int t=0;t<8;t++){
                int n0=wn*64+t*8+g;
                int i0=(k0+tg)*SX+n0, i1=(k0+4+tg)*SX+n0;
                uint32_t b0h=xh[i0], b1h=xh[i1], b0l=xl[i0], b1l=xl[i1];
                mma8(acc[t],Ah,b0h,b1h);
                mma8(acc[t],Ah,b0l,b1l);
                mma8(acc[t],Al,b0h,b1h);
            }
        }
    }
    float* ob = outp + bbase + nblk;
    #pragma unroll
    for (int t=0;t<8;t++){
        int n0 = wn*64 + t*8 + 2*tg;
        int r0 = wm*16 + g;
        float2 v0 = make_float2(acc[t][0],acc[t][1]);
        float2 v1 = make_float2(acc[t][2],acc[t][3]);
        if (NB>0){ float b0v=bs[r0], b1v=bs[r0+8];
                   v0.x+=b0v; v0.y+=b0v; v1.x+=b1v; v1.y+=b1v; }
        if (GELU){ v0.x=gelu_f(v0.x); v0.y=gelu_f(v0.y); v1.x=gelu_f(v1.x); v1.y=gelu_f(v1.y); }
        *(float2*)(ob + (size_t)r0*NN + n0)     = v0;
        *(float2*)(ob + (size_t)(r0+8)*NN + n0) = v1;
    }
}

// =====================================================================
// Fused row attention: per block (b,r): S=K^T Q (mma), softmax over j,
// O = V P (mma), out = gamma*O/l + res.   Layouts all [b][c][r][i].
// =====================================================================
#define SL 192
#define SSP 200
#define SQP 200
#define SKP 72
#define SVP 68
#define FA_SMEM ((SL*SSP + CC*SQP + CC*SKP + SL)*4)

__global__ __launch_bounds__(256,1)
void fattn_k(const float* __restrict__ Q, const float* __restrict__ K,
             const float* __restrict__ V, const float* __restrict__ res,
             const float* __restrict__ gamma_p, float* __restrict__ out){
    extern __shared__ float sm[];
    float* sS  = sm;                  // [192][200]
    float* sQ  = sS + SL*SSP;         // [64][200]
    float* sKV = sQ + CC*SQP;         // [64][72] / [64][68]
    float* sL  = sKV + CC*SKP;        // [192]
    int tid=threadIdx.x, wid=tid>>5, lane=tid&31;
    int b = blockIdx.x / HH, r = blockIdx.x % HH;
    size_t base = (size_t)b*CC*NN + (size_t)r*WW;
    // stage Q [c][i]
    {
        int c = tid>>2, p = tid&3;
        const float2* src = (const float2*)(Q + base + (size_t)c*NN);
        float2* dst = (float2*)(sQ + c*SQP);
        #pragma unroll
        for(int u=0;u<24;u++) dst[p*24+u] = src[p*24+u];
    }
    int wm = wid&1, wn = wid>>1;
    int g = lane>>2, tg = lane&3;
    float acc[12][4];
    // ---- phase 1: S[j][i] = sum_c K[c][j] Q[c][i] ----
    for (int jt=0;jt<3;jt++){
        __syncthreads();
        {
            int c = tid>>2, p = tid&3;
            const float4* src = (const float4*)(K + base + (size_t)c*NN + jt*64);
            float4* dst = (float4*)(sKV + c*SKP);
            #pragma unroll
            for(int u=0;u<4;u++) dst[p*4+u] = src[p*4+u];
        }
        __syncthreads();
        #pragma unroll
        for(int t=0;t<12;t++){acc[t][0]=0;acc[t][1]=0;acc[t][2]=0;acc[t][3]=0;}
        #pragma unroll
        for(int kc=0;kc<8;kc++){
            int k0=kc*8;
            uint32_t Ah[2][4], Al[2][4];
            #pragma unroll
            for(int mt=0;mt<2;mt++){
                int m0 = wm*32+mt*16;
                #pragma unroll
                for(int e=0;e<4;e++){
                    int kk = k0 + tg + (e>>1)*4;
                    int mm = m0 + g + (e&1)*8;
                    float v = sKV[kk*SKP + mm];
                    uint32_t h=f2tf(v); Ah[mt][e]=h; Al[mt][e]=f2tf(v-__uint_as_float(h));
                }
            }
            #pragma unroll
            for(int nt=0;nt<6;nt++){
                int n0 = wn*48+nt*8;
                float v0 = sQ[(k0+tg)*SQP + n0+g];
                float v1 = sQ[(k0+tg+4)*SQP + n0+g];
                uint32_t b0h=f2tf(v0), b1h=f2tf(v1);
                uint32_t b0l=f2tf(v0-__uint_as_float(b0h)), b1l=f2tf(v1-__uint_as_float(b1h));
                #pragma unroll
                for(int mt=0;mt<2;mt++){
                    float* a = acc[mt*6+nt];
                    mma8(a,Ah[mt],b0h,b1h);
                    mma8(a,Ah[mt],b0l,b1l);
                    mma8(a,Al[mt],b0h,b1h);
                }
            }
        }
        #pragma unroll
        for(int mt=0;mt<2;mt++){
            int j0 = jt*64 + wm*32 + mt*16;
            #pragma unroll
            for(int nt=0;nt<6;nt++){
                int n0 = wn*48+nt*8;
                float* a = acc[mt*6+nt];
                *(float2*)&sS[(j0+g)*SSP + n0+2*tg]   = make_float2(a[0],a[1]);
                *(float2*)&sS[(j0+8+g)*SSP + n0+2*tg] = make_float2(a[2],a[3]);
            }
        }
    }
    __syncthreads();
    // ---- softmax over j per column i (unnormalized; 1/l in epilogue) ----
    if (tid < SL){
        int i = tid;
        float m = -3.4e38f;
        #pragma unroll 8
        for(int j=0;j<SL;j++) m = fmaxf(m, sS[j*SSP+i]);
        float s = 0.f;
        #pragma unroll 8
        for(int j=0;j<SL;j++){ float e = __expf(sS[j*SSP+i]-m); sS[j*SSP+i]=e; s+=e; }
        sL[i] = 1.f/s;
    }
    // ---- phase 2: O[c][i] = sum_j V[c][j] P[j][i] ----
    #pragma unroll
    for(int t=0;t<12;t++){acc[t][0]=0;acc[t][1]=0;acc[t][2]=0;acc[t][3]=0;}
    for (int jt=0;jt<3;jt++){
        __syncthreads();
        {
            int c = tid>>2, p = tid&3;
            const float4* src = (const float4*)(V + base + (size_t)c*NN + jt*64);
            float4* dst = (float4*)(sKV + c*SVP);
            #pragma unroll
            for(int u=0;u<4;u++) dst[p*4+u] = src[p*4+u];
        }
        __syncthreads();
        #pragma unroll
        for(int kc=0;kc<8;kc++){
            int k0 = jt*64 + kc*8;
            int kk0 = kc*8;
            uint32_t Ah[2][4], Al[2][4];
            #pragma unroll
            for(int mt=0;mt<2;mt++){
                int m0 = wm*32+mt*16;
                #pragma unroll
                for(int e=0;e<4;e++){
                    int kk = kk0 + tg + (e>>1)*4;
                    int mm = m0 + g + (e&1)*8;
                    float v = sKV[mm*SVP + kk];
                    uint32_t h=f2tf(v); Ah[mt][e]=h; Al[mt][e]=f2tf(v-__uint_as_float(h));
                }
            }
            #pragma unroll
            for(int nt=0;nt<6;nt++){
                int n0 = wn*48+nt*8;
                float v0 = sS[(k0+tg)*SSP + n0+g];
                float v1 = sS[(k0+tg+4)*SSP + n0+g];
                uint32_t b0h=f2tf(v0), b1h=f2tf(v1);
                uint32_t b0l=f2tf(v0-__uint_as_float(b0h)), b1l=f2tf(v1-__uint_as_float(b1h));
                #pragma unroll
                for(int mt=0;mt<2;mt++){
                    float* a = acc[mt*6+nt];
                    mma8(a,Ah[mt],b0h,b1h);
                    mma8(a,Ah[mt],b0l,b1l);
                    mma8(a,Al[mt],b0h,b1h);
                }
            }
        }
    }
    // ---- epilogue ----
    float gm = gamma_p[0];
    #pragma unroll
    for(int mt=0;mt<2;mt++){
        int m0 = wm*32+mt*16;
        #pragma unroll
        for(int nt=0;nt<6;nt++){
            int n0 = wn*48+nt*8 + 2*tg;
            float il0 = sL[n0], il1 = sL[n0+1];
            float* a = acc[mt*6+nt];
            float2 r0 = *(const float2*)(res + base + (size_t)(m0+g)*NN + n0);
            float2 r1 = *(const float2*)(res + base + (size_t)(m0+8+g)*NN + n0);
            *(float2*)(out + base + (size_t)(m0+g)*NN + n0) =
                make_float2(gm*a[0]*il0 + r0.x, gm*a[1]*il1 + r0.y);
            *(float2*)(out + base + (size_t)(m0+8+g)*NN + n0) =
                make_float2(gm*a[2]*il0 + r1.x, gm*a[3]*il1 + r1.y);
        }
    }
}

// ---------------- depthwise 3x3 + bias + gelu ----------------
__global__ void dwconv_k(const float* __restrict__ in, const float* __restrict__ w,
                         const float* __restrict__ bias, float* __restrict__ out){
    int idx = blockIdx.x*blockDim.x + threadIdx.x;
    if (idx >= BB*CC*NN) return;
    int n = idx % NN; int bc = idx / NN; int c = bc % CC;
    int y = n / WW, x = n % WW;
    const float* wp = w + c*9;
    const float* ip = in + (size_t)bc*NN;
    float acc = bias[c];
    #pragma unroll
    for (int ky=0;ky<3;ky++){
        int yy = y+ky-1; if (yy<0||yy>=HH) continue;
        #pragma unroll
        for (int kx=0;kx<3;kx++){
            int xx = x+kx-1; if (xx<0||xx>=WW) continue;
            acc += wp[ky*3+kx]*ip[(size_t)yy*WW+xx];
        }
    }
    out[idx] = gelu_f(acc);
}

// ---------------- transpose [b,c,H,W] -> [b,c,W,H] ----------------
__global__ void transpose_k(const float* __restrict__ in, float* __restrict__ out){
    __shared__ float t[32][33];
    const float* ib = in + (size_t)blockIdx.z*NN;
    float* ob = out + (size_t)blockIdx.z*NN;
    int x = blockIdx.x*32 + threadIdx.x;
    #pragma unroll
    for (int k=0;k<32;k+=8)
        t[threadIdx.y+k][threadIdx.x] = ib[(size_t)(blockIdx.y*32+threadIdx.y+k)*WW + x];
    __syncthreads();
    int x2 = blockIdx.y*32 + threadIdx.x;
    #pragma unroll
    for (int k=0;k<32;k+=8)
        ob[(size_t)(blockIdx.x*32+threadIdx.y+k)*HH + x2] = t[threadIdx.x][threadIdx.y+k];
}

// ---------------- q,k row sum-of-squares ----------------
__global__ void norm_k(const float* __restrict__ q, const float* __restrict__ k){
    int id = blockIdx.x;
    const float* src = (id < BB*CC) ? q : k;
    int bc = id % (BB*CC);
    const float* r = src + (size_t)bc*NN;
    float s=0.f;
    for (int n=threadIdx.x;n<NN;n+=256){ float v=r[n]; s+=v*v; }
    __shared__ float red[256];
    red[threadIdx.x]=s; __syncthreads();
    for (int o=128;o;o>>=1){ if(threadIdx.x<o) red[threadIdx.x]+=red[threadIdx.x+o]; __syncthreads(); }
    if (threadIdx.x==0) g_norm[id]=red[0];
}

__global__ void zero_attn_k(){
    int i = blockIdx.x*blockDim.x+threadIdx.x;
    if (i < BB*NHEADS*32*32) g_attn[i]=0.f;
}

// ---------------- channel-attn gram (chunked atomics) ----------------
#define NCHUNK 32
#define CHUNK (NN/NCHUNK)
__global__ void gram_k(const float* __restrict__ q, const float* __restrict__ k){
    int bg = blockIdx.x; int b=bg/NHEADS, g=bg%NHEADS;
    int n0 = blockIdx.y*CHUNK;
    __shared__ float qs[64][33], ks[64][33];
    int c = threadIdx.x>>3, dg = threadIdx.x&7;
    float a0=0,a1=0,a2=0,a3=0;
    const float* qb = q + ((size_t)(b*CC + g*32))*NN + n0;
    const float* kb = k + ((size_t)(b*CC + g*32))*NN + n0;
    for (int tt=0;tt<CHUNK;tt+=64){
        __syncthreads();
        for (int e=threadIdx.x;e<32*64;e+=256){
            int cc=e>>6, t=e&63;
            qs[t][cc]=qb[(size_t)cc*NN + tt + t];
            ks[t][cc]=kb[(size_t)cc*NN + tt + t];
        }
        __syncthreads();
        #pragma unroll 8
        for (int t=0;t<64;t++){
            float qv=qs[t][c];
            a0+=qv*ks[t][dg];    a1+=qv*ks[t][dg+8];
            a2+=qv*ks[t][dg+16]; a3+=qv*ks[t][dg+24];
        }
    }
    float* ab = g_attn + ((size_t)(bg*32+c))*32;
    atomicAdd(&ab[dg],a0);    atomicAdd(&ab[dg+8],a1);
    atomicAdd(&ab[dg+16],a2); atomicAdd(&ab[dg+24],a3);
}

// ---------------- channel-attn softmax ----------------
__global__ void chsm_k(const float* __restrict__ temp){
    int bg = blockIdx.x; int b=bg/NHEADS, g=bg%NHEADS;
    int c = threadIdx.x>>5, d = threadIdx.x&31;
    float nq = fmaxf(sqrtf(g_norm[b*CC + g*32 + c]), 1e-12f);
    float nk = fmaxf(sqrtf(g_norm[BB*CC + b*CC + g*32 + d]), 1e-12f);
    int idx = (bg*32+c)*32+d;
    float v = g_attn[idx]/(nq*nk)*temp[g];
    float m=v;
    #pragma unroll
    for (int o=16;o;o>>=1) m=fmaxf(m,__shfl_xor_sync(0xffffffffu,m,o));
    float e=expf(v-m), s=e;
    #pragma unroll
    for (int o=16;o;o>>=1) s+=__shfl_xor_sync(0xffffffffu,s,o);
    g_attn[idx]=e/s;
}

// ---------------- mid = attn @ v ----------------
__global__ void attnv_k(const float* __restrict__ v, float* __restrict__ mid){
    __shared__ float4 as4[NHEADS*32*8];
    int b = blockIdx.y;
    int n = blockIdx.x*256 + threadIdx.x;
    const float4* ag = (const float4*)(g_attn + b*NHEADS*32*32);
    for (int i=threadIdx.x;i<NHEADS*32*8;i+=256) as4[i]=ag[i];
    __syncthreads();
    const float* vb = v + (size_t)b*CC*NN + n;
    float* mb = mid + (size_t)b*CC*NN + n;
    #pragma unroll
    for (int g=0;g<NHEADS;g++){
        float vv[32];
        #pragma unroll
        for (int d=0;d<32;d++) vv[d]=vb[(size_t)(g*32+d)*NN];
        #pragma unroll 1
        for (int c=0;c<32;c++){
            float a=0.f;
            #pragma unroll
            for (int d4=0;d4<8;d4++){
                float4 av=as4[(g*32+c)*8+d4];
                a += av.x*vv[d4*4]+av.y*vv[d4*4+1]+av.z*vv[d4*4+2]+av.w*vv[d4*4+3];
            }
            mb[(size_t)(g*32+c)*NN]=a;
        }
    }
}

// =======================================================================
extern "C" void kernel_launch(void* const* d_in, const int* in_sizes, int n_in,
                              void* d_out, int out_size){
    const float* x      =(const float*)d_in[0];
    const float* pw_w   =(const float*)d_in[1];
    const float* dw_w   =(const float*)d_in[2];
    const float* dw_b   =(const float*)d_in[3];
    const float* conv2_w=(const float*)d_in[4];
    const float* conv2_b=(const float*)d_in[5];
    const float* conv0_w=(const float*)d_in[6];
    const float* conv0_b=(const float*)d_in[7];
    const float* att_q_w=(const float*)d_in[8];
    const float* att_k_w=(const float*)d_in[9];
    const float* att_v_w=(const float*)d_in[10];
    const float* att_p_w=(const float*)d_in[11];
    const float* temp   =(const float*)d_in[12];
    const float* row_q_w=(const float*)d_in[13];
    const float* row_k_w=(const float*)d_in[14];
    const float* row_v_w=(const float*)d_in[15];
    const float* row_g  =(const float*)d_in[16];
    const float* col_q_w=(const float*)d_in[17];
    const float* col_k_w=(const float*)d_in[18];
    const float* col_v_w=(const float*)d_in[19];
    const float* col_g  =(const float*)d_in[20];
    const float* conv_w =(const float*)d_in[21];
    const float* conv_b =(const float*)d_in[22];
    float* out=(float*)d_out;

    float *t0,*t1,*x1b,*q,*k,*v,*o1,*o2,*o3;
    cudaGetSymbolAddress((void**)&t0,  g_t0);
    cudaGetSymbolAddress((void**)&t1,  g_t1);
    cudaGetSymbolAddress((void**)&x1b, g_x1);
    cudaGetSymbolAddress((void**)&q,   g_q);
    cudaGetSymbolAddress((void**)&k,   g_k);
    cudaGetSymbolAddress((void**)&v,   g_v);
    cudaGetSymbolAddress((void**)&o1,  g_o1);
    cudaGetSymbolAddress((void**)&o2,  g_o2);
    cudaGetSymbolAddress((void**)&o3,  g_o3);

    const int SM_Q1 = (2*CC*SX + 1*2*CC*SWT)*4;
    const int SM_Q2 = (2*CC*SX + 2*2*CC*SWT)*4;
    const int SM_Q3 = (2*CC*SX + 3*2*CC*SWT)*4;
    const int SM_CM = (2*CC*SX + 2*CC*SWT)*4;
    cudaFuncSetAttribute(qkvmma_k<1>, cudaFuncAttributeMaxDynamicSharedMemorySize, SM_Q1);
    cudaFuncSetAttribute(qkvmma_k<2>, cudaFuncAttributeMaxDynamicSharedMemorySize, SM_Q2);
    cudaFuncSetAttribute(qkvmma_k<3>, cudaFuncAttributeMaxDynamicSharedMemorySize, SM_Q3);
    cudaFuncSetAttribute(cmma_k<2,2,false>, cudaFuncAttributeMaxDynamicSharedMemorySize, SM_CM);
    cudaFuncSetAttribute(cmma_k<3,1,true>,  cudaFuncAttributeMaxDynamicSharedMemorySize, SM_CM);
    cudaFuncSetAttribute(fattn_k, cudaFuncAttributeMaxDynamicSharedMemorySize, FA_SMEM);

    dim3 mg(NN/128, BB);
    dim3 cg(NN/256, BB);

    // ---- BSConvU + skip -> x1 ----
    zero_attn_k<<<32,256>>>();
    qkvmma_k<1><<<mg,256,SM_Q1>>>(x, pw_w,nullptr,nullptr, t0,nullptr,nullptr);
    dwconv_k<<<(BB*CC*NN)/256,256>>>(t0, dw_w, dw_b, t1);
    cmma_k<2,2,false><<<mg,256,SM_CM>>>(t1,x,nullptr, conv2_w,conv0_w,nullptr, 64,
                                        conv2_b,conv0_b, x1b);

    // ---- channel self-attention -> o1 ----
    qkvmma_k<3><<<mg,256,SM_Q3>>>(x1b, att_q_w,att_k_w,att_v_w, q,k,v);
    norm_k<<<2*BB*CC,256>>>(q,k);
    gram_k<<<dim3(BB*NHEADS,NCHUNK),256>>>(q,k);
    chsm_k<<<BB*NHEADS,1024>>>(temp);
    attnv_k<<<cg,256>>>(v, t0);
    qkvmma_k<1><<<mg,256,SM_Q1>>>(t0, att_p_w,nullptr,nullptr, o1,nullptr,nullptr);

    // ---- row attention -> o2 (fused gram+softmax+apply+residual) ----
    qkvmma_k<2><<<mg,256,SM_Q2>>>(x1b, row_q_w,row_k_w,nullptr, q,k,nullptr);
    qkvmma_k<1><<<mg,256,SM_Q1>>>(o1, row_v_w,nullptr,nullptr, v,nullptr,nullptr);
    fattn_k<<<BB*HH,256,FA_SMEM>>>(q,k,v,x1b,row_g,o2);

    // ---- col attention (transposed) -> o3 ----
    transpose_k<<<dim3(6,6,BB*CC),dim3(32,8)>>>(x1b, t1);
    transpose_k<<<dim3(6,6,BB*CC),dim3(32,8)>>>(o1,  t0);
    qkvmma_k<2><<<mg,256,SM_Q2>>>(t1, col_q_w,col_k_w,nullptr, q,k,nullptr);
    qkvmma_k<1><<<mg,256,SM_Q1>>>(t0, col_v_w,nullptr,nullptr, v,nullptr,nullptr);
    fattn_k<<<BB*WW,256,FA_SMEM>>>(q,k,v,t1,col_g,t0);
    transpose_k<<<dim3(6,6,BB*CC),dim3(32,8)>>>(t0, o3);

    // ---- fuse ----
    cmma_k<3,1,true><<<mg,256,SM_CM>>>(o1,o2,o3, conv_w,conv_w+64,conv_w+128, 192,
                                       conv_b,nullptr, out);
}

// round 9
// speedup vs baseline: 2.7652x; 1.3319x over previous
#include <cuda_runtime.h>
#include <cuda_bf16.h>
#include <math.h>
#include <stdint.h>

#define BB 4
#define CC 64
#define HH 192
#define WW 192
#define NN (HH*WW)          // 36864
#define PP (BB*NN)
#define NHEADS 2

// ---------------- scratch ----------------
__device__ float g_t0[BB*CC*NN];
__device__ float g_t1[BB*CC*NN];
__device__ float g_x1[BB*CC*NN];
__device__ float g_q [BB*CC*NN];
__device__ float g_k [BB*CC*NN];
__device__ float g_v [BB*CC*NN];
__device__ float g_o1[BB*CC*NN];
__device__ float g_o2[BB*CC*NN];
__device__ float g_o3[BB*CC*NN];
__device__ float g_norm[2*BB*CC];
__device__ float g_attn[BB*NHEADS*32*32];

__device__ __forceinline__ float gelu_f(float v){
    return 0.5f*v*(1.f+erff(v*0.70710678118654752f));
}
// pack two floats as bf16x2: 'lo' -> low 16 bits (even k), 'hi' -> high 16 bits (odd k)
__device__ __forceinline__ uint32_t packbf(float lo, float hi){
    uint32_t r; asm("cvt.rn.bf16x2.f32 %0, %1, %2;" : "=r"(r) : "f"(hi), "f"(lo)); return r;
}
__device__ __forceinline__ float bfhi(float v){
    return __bfloat162float(__float2bfloat16(v));
}
__device__ __forceinline__ void mma16(float* d, const uint32_t* a, uint32_t b0, uint32_t b1){
    asm("mma.sync.aligned.m16n8k16.row.col.f32.bf16.bf16.f32 "
        "{%0,%1,%2,%3},{%4,%5,%6,%7},{%8,%9},{%0,%1,%2,%3};"
        : "+f"(d[0]),"+f"(d[1]),"+f"(d[2]),"+f"(d[3])
        : "r"(a[0]),"r"(a[1]),"r"(a[2]),"r"(a[3]),"r"(b0),"r"(b1));
}
// a = even-channel 4 pixels, b = odd-channel 4 pixels -> 4 hi words + 4 lo words
__device__ __forceinline__ void stage_pair4(uint32_t* hp, uint32_t* lp, float4 a, float4 b){
    uint4 h, l;
    h.x=packbf(a.x,b.x); h.y=packbf(a.y,b.y); h.z=packbf(a.z,b.z); h.w=packbf(a.w,b.w);
    l.x=packbf(a.x-bfhi(a.x), b.x-bfhi(b.x));
    l.y=packbf(a.y-bfhi(a.y), b.y-bfhi(b.y));
    l.z=packbf(a.z-bfhi(a.z), b.z-bfhi(b.z));
    l.w=packbf(a.w-bfhi(a.w), b.w-bfhi(b.w));
    *(uint4*)hp = h; *(uint4*)lp = l;
}

#define XR 136                // conv X smem row stride (words per k-pair row, 128 px + pad)
#define WR 36                 // conv W smem row stride
#define XW_WORDS (32*XR)      // 4352
#define WW_WORDS (64*WR)      // 2304

// =====================================================================
// QKV-style bf16-split mma conv: NS weight sets sharing one input. K=64.
// Block: 64 out-ch x 128 px. grid(NN/128, BB), 256 thr.
// =====================================================================
template<int NS>
__global__ __launch_bounds__(256, NS==1?2:1)
void qkvmma_k(const float* __restrict__ in,
              const float* __restrict__ w0,const float* __restrict__ w1,const float* __restrict__ w2,
              float* __restrict__ p0,float* __restrict__ p1,float* __restrict__ p2){
    extern __shared__ uint32_t smu[];
    uint32_t* xh = smu;
    uint32_t* xl = xh + XW_WORDS;
    uint32_t* wsm= xl + XW_WORDS;     // per set: [hi 2304][lo 2304]
    int tid=threadIdx.x, wid=tid>>5, lane=tid&31;
    const float* wptr[3]={w0,w1,w2};
    float* optr[3]={p0,p1,p2};
    size_t bbase=(size_t)blockIdx.y*CC*NN;
    int nblk=blockIdx.x*128;
    const float* ib = in + bbase + nblk;
    // stage X as bf16 hi/lo channel-pair words [k2][n]
    {
        int c2=tid>>3, pp=(tid&7)*16;
        const float* r0 = ib + (size_t)(2*c2)*NN;
        const float* r1 = r0 + NN;
        #pragma unroll
        for (int u=0;u<4;u++){
            float4 a=*(const float4*)(r0+pp+u*4);
            float4 b=*(const float4*)(r1+pp+u*4);
            stage_pair4(&xh[c2*XR+pp+u*4], &xl[c2*XR+pp+u*4], a, b);
        }
    }
    // stage W [m][k2]
    #pragma unroll
    for (int s=0;s<NS;s++){
        const float* wp=wptr[s];
        uint32_t* wh = wsm + s*2*WW_WORDS;
        uint32_t* wl = wh + WW_WORDS;
        #pragma unroll
        for (int i=0;i<4;i++){
            int idx=tid+i*256; int o=idx>>4, c4=idx&15;
            float4 v=*(const float4*)(wp + o*64 + c4*4);
            uint2 h,l;
            h.x=packbf(v.x,v.y); h.y=packbf(v.z,v.w);
            l.x=packbf(v.x-bfhi(v.x), v.y-bfhi(v.y));
            l.y=packbf(v.z-bfhi(v.z), v.w-bfhi(v.w));
            *(uint2*)&wh[o*WR+2*c4]=h;
            *(uint2*)&wl[o*WR+2*c4]=l;
        }
    }
    __syncthreads();
    int wm=wid&3, wn=wid>>2, g=lane>>2, tg=lane&3;
    float acc[NS][8][4];
    #pragma unroll
    for (int s=0;s<NS;s++)
        #pragma unroll
        for (int t=0;t<8;t++)
            #pragma unroll
            for (int e=0;e<4;e++) acc[s][t][e]=0.f;
    #pragma unroll
    for (int ks=0;ks<4;ks++){
        int k2=ks*8;
        uint32_t B0h[8],B1h[8],B0l[8],B1l[8];
        #pragma unroll
        for (int t=0;t<8;t++){
            int n0=wn*64+t*8+g;
            int i0=(k2+tg)*XR+n0, i1=(k2+4+tg)*XR+n0;
            B0h[t]=xh[i0]; B1h[t]=xh[i1];
            B0l[t]=xl[i0]; B1l[t]=xl[i1];
        }
        #pragma unroll
        for (int s=0;s<NS;s++){
            const uint32_t* wh = wsm + s*2*WW_WORDS;
            const uint32_t* wl = wh + WW_WORDS;
            int r0=(wm*16+g)*WR+k2+tg, r1=(wm*16+8+g)*WR+k2+tg;
            uint32_t Ah[4]={wh[r0],wh[r1],wh[r0+4],wh[r1+4]};
            uint32_t Al[4]={wl[r0],wl[r1],wl[r0+4],wl[r1+4]};
            #pragma unroll
            for (int t=0;t<8;t++){
                mma16(acc[s][t],Ah,B0h[t],B1h[t]);
                mma16(acc[s][t],Ah,B0l[t],B1l[t]);
                mma16(acc[s][t],Al,B0h[t],B1h[t]);
            }
        }
    }
    #pragma unroll
    for (int s=0;s<NS;s++){
        float* ob = optr[s] + bbase + nblk;
        #pragma unroll
        for (int t=0;t<8;t++){
            int n0 = wn*64 + t*8 + 2*tg;
            int r0 = wm*16 + g;
            *(float2*)(ob + (size_t)r0*NN + n0)     = make_float2(acc[s][t][0],acc[s][t][1]);
            *(float2*)(ob + (size_t)(r0+8)*NN + n0) = make_float2(acc[s][t][2],acc[s][t][3]);
        }
    }
}

// =====================================================================
// K-concat bf16-split mma conv
// =====================================================================
template<int NC,int NB,bool GELU>
__global__ __launch_bounds__(256,2)
void cmma_k(const float* __restrict__ in0,const float* __restrict__ in1,const float* __restrict__ in2,
            const float* __restrict__ w0,const float* __restrict__ w1,const float* __restrict__ w2,
            int wstride,
            const float* __restrict__ bias0,const float* __restrict__ bias1,
            float* __restrict__ outp){
    extern __shared__ uint32_t smu[];
    uint32_t* xh = smu;
    uint32_t* xl = xh + XW_WORDS;
    uint32_t* wh = xl + XW_WORDS;
    uint32_t* wl = wh + WW_WORDS;
    __shared__ float bs[CC];
    int tid=threadIdx.x, wid=tid>>5, lane=tid&31;
    if (NB>0 && tid<CC){ float bv=bias0[tid]; if (NB>1) bv+=bias1[tid]; bs[tid]=bv; }
    const float* ip[3]={in0,in1,in2};
    const float* wp[3]={w0,w1,w2};
    size_t bbase=(size_t)blockIdx.y*CC*NN;
    int nblk=blockIdx.x*128;
    int wm=wid&3, wn=wid>>2, g=lane>>2, tg=lane&3;
    float acc[8][4];
    #pragma unroll
    for (int t=0;t<8;t++){ acc[t][0]=0;acc[t][1]=0;acc[t][2]=0;acc[t][3]=0; }
    #pragma unroll 1
    for (int c=0;c<NC;c++){
        if (c) __syncthreads();
        {
            int c2=tid>>3, pp=(tid&7)*16;
            const float* r0 = ip[c] + bbase + nblk + (size_t)(2*c2)*NN;
            const float* r1 = r0 + NN;
            #pragma unroll
            for (int u=0;u<4;u++){
                float4 a=*(const float4*)(r0+pp+u*4);
                float4 b=*(const float4*)(r1+pp+u*4);
                stage_pair4(&xh[c2*XR+pp+u*4], &xl[c2*XR+pp+u*4], a, b);
            }
        }
        const float* wpc = wp[c];
        #pragma unroll
        for (int i=0;i<4;i++){
            int idx=tid+i*256; int o=idx>>4, c4=idx&15;
            float4 v=*(const float4*)(wpc + (size_t)o*wstride + c4*4);
            uint2 h,l;
            h.x=packbf(v.x,v.y); h.y=packbf(v.z,v.w);
            l.x=packbf(v.x-bfhi(v.x), v.y-bfhi(v.y));
            l.y=packbf(v.z-bfhi(v.z), v.w-bfhi(v.w));
            *(uint2*)&wh[o*WR+2*c4]=h;
            *(uint2*)&wl[o*WR+2*c4]=l;
        }
        __syncthreads();
        #pragma unroll
        for (int ks=0;ks<4;ks++){
            int k2=ks*8;
            int r0=(wm*16+g)*WR+k2+tg, r1=(wm*16+8+g)*WR+k2+tg;
            uint32_t Ah[4]={wh[r0],wh[r1],wh[r0+4],wh[r1+4]};
            uint32_t Al[4]={wl[r0],wl[r1],wl[r0+4],wl[r1+4]};
            #pragma unroll
            for (int t=0;t<8;t++){
                int n0=wn*64+t*8+g;
                int i0=(k2+tg)*XR+n0, i1=(k2+4+tg)*XR+n0;
                uint32_t b0h=xh[i0], b1h=xh[i1], b0l=xl[i0], b1l=xl[i1];
                mma16(acc[t],Ah,b0h,b1h);
                mma16(acc[t],Ah,b0l,b1l);
                mma16(acc[t],Al,b0h,b1h);
            }
        }
    }
    float* ob = outp + bbase + nblk;
    #pragma unroll
    for (int t=0;t<8;t++){
        int n0 = wn*64 + t*8 + 2*tg;
        int r0 = wm*16 + g;
        float2 v0 = make_float2(acc[t][0],acc[t][1]);
        float2 v1 = make_float2(acc[t][2],acc[t][3]);
        if (NB>0){ float b0v=bs[r0], b1v=bs[r0+8];
                   v0.x+=b0v; v0.y+=b0v; v1.x+=b1v; v1.y+=b1v; }
        if (GELU){ v0.x=gelu_f(v0.x); v0.y=gelu_f(v0.y); v1.x=gelu_f(v1.x); v1.y=gelu_f(v1.y); }
        *(float2*)(ob + (size_t)r0*NN + n0)     = v0;
        *(float2*)(ob + (size_t)(r0+8)*NN + n0) = v1;
    }
}

// =====================================================================
// Fused row attention (bf16-split mma): per block (b,r).
// S = K^T Q; softmax over j (packed in place); O = V P; out = gm*O/l + res
// =====================================================================
#define SL 192
#define SSP 204
#define SKP 76
#define SVP 72
#define QR 200   // fattn Q stride: 192 cols + 8 pad (192 > conv's 128!)
#define FA_SMEM ((SL*SSP + 2*32*QR + 64*SKP + SL)*4)   // 228096 B

__global__ __launch_bounds__(256,1)
void fattn_k(const float* __restrict__ Q, const float* __restrict__ K,
             const float* __restrict__ V, const float* __restrict__ res,
             const float* __restrict__ gamma_p, float* __restrict__ out){
    extern __shared__ float sm[];
    float*    sS = sm;                      // [192][204] fp32 scores -> packed P
    uint32_t* qh = (uint32_t*)(sS + SL*SSP);// [32][200]
    uint32_t* ql = qh + 32*QR;
    float*    sKV= (float*)(ql + 32*QR);    // [64][76] K / [64][72] V
    float*    sL = sKV + 64*SKP;            // [192]
    int tid=threadIdx.x, wid=tid>>5, lane=tid&31;
    int b = blockIdx.x / HH, r = blockIdx.x % HH;
    size_t base = (size_t)b*CC*NN + (size_t)r*WW;
    // stage Q as bf16 hi/lo channel-pair words [k2][i]
    {
        int c2=tid>>3, pp=(tid&7)*24;
        const float* r0 = Q + base + (size_t)(2*c2)*NN;
        const float* r1 = r0 + NN;
        #pragma unroll
        for (int u=0;u<6;u++){
            float4 a=*(const float4*)(r0+pp+u*4);
            float4 b4=*(const float4*)(r1+pp+u*4);
            stage_pair4(&qh[c2*QR+pp+u*4], &ql[c2*QR+pp+u*4], a, b4);
        }
    }
    int wm = wid&1, wn = wid>>1;
    int g = lane>>2, tg = lane&3;
    float acc[12][4];
    // ---- phase 1: S[j][i] = sum_c K[c][j] Q[c][i] ----
    for (int jt=0;jt<3;jt++){
        __syncthreads();
        {
            int c = tid>>2, p = tid&3;
            const float4* src = (const float4*)(K + base + (size_t)c*NN + jt*64);
            #pragma unroll
            for (int u=0;u<4;u++)
                *(float4*)(sKV + c*SKP + p*16 + u*4) = src[p*4+u];
        }
        __syncthreads();
        #pragma unroll
        for (int t=0;t<12;t++){acc[t][0]=0;acc[t][1]=0;acc[t][2]=0;acc[t][3]=0;}
        #pragma unroll
        for (int kc=0;kc<4;kc++){
            int k0=kc*16, k2=kc*8;
            uint32_t Ah[2][4], Al[2][4];
            #pragma unroll
            for (int mt=0;mt<2;mt++){
                int m0 = wm*32+mt*16;
                #pragma unroll
                for (int w=0;w<4;w++){
                    int cb  = k0 + 2*tg + (w>>1)*8;
                    int row = m0 + g + (w&1)*8;
                    float v0 = sKV[cb*SKP+row], v1 = sKV[(cb+1)*SKP+row];
                    Ah[mt][w]=packbf(v0,v1);
                    Al[mt][w]=packbf(v0-bfhi(v0), v1-bfhi(v1));
                }
            }
            #pragma unroll
            for (int nt=0;nt<6;nt++){
                int n0 = wn*48+nt*8+g;
                uint32_t b0h=qh[(k2+tg)*QR+n0],   b1h=qh[(k2+4+tg)*QR+n0];
                uint32_t b0l=ql[(k2+tg)*QR+n0],   b1l=ql[(k2+4+tg)*QR+n0];
                #pragma unroll
                for (int mt=0;mt<2;mt++){
                    float* a = acc[mt*6+nt];
                    mma16(a,Ah[mt],b0h,b1h);
                    mma16(a,Ah[mt],b0l,b1l);
                    mma16(a,Al[mt],b0h,b1h);
                }
            }
        }
        #pragma unroll
        for (int mt=0;mt<2;mt++){
            int j0 = jt*64 + wm*32 + mt*16;
            #pragma unroll
            for (int nt=0;nt<6;nt++){
                int n0 = wn*48+nt*8;
                float* a = acc[mt*6+nt];
                *(float2*)&sS[(j0+g)*SSP + n0+2*tg]   = make_float2(a[0],a[1]);
                *(float2*)&sS[(j0+8+g)*SSP + n0+2*tg] = make_float2(a[2],a[3]);
            }
        }
    }
    __syncthreads();
    // ---- softmax over j per column i, pack P in place (even row=hi, odd=lo) ----
    if (tid < SL){
        int i = tid;
        float m = -3.4e38f;
        #pragma unroll 8
        for (int j=0;j<SL;j++) m = fmaxf(m, sS[j*SSP+i]);
        float s = 0.f;
        #pragma unroll 4
        for (int j2=0;j2<SL/2;j2++){
            float e0 = __expf(sS[(2*j2)*SSP+i]-m);
            float e1 = __expf(sS[(2*j2+1)*SSP+i]-m);
            s += e0+e1;
            sS[(2*j2)*SSP+i]   = __uint_as_float(packbf(e0,e1));
            sS[(2*j2+1)*SSP+i] = __uint_as_float(packbf(e0-bfhi(e0), e1-bfhi(e1)));
        }
        sL[i] = 1.f/s;
    }
    // ---- phase 2: O[c][i] = sum_j V[c][j] P[j][i] ----
    #pragma unroll
    for (int t=0;t<12;t++){acc[t][0]=0;acc[t][1]=0;acc[t][2]=0;acc[t][3]=0;}
    for (int jt=0;jt<3;jt++){
        __syncthreads();
        {
            int c = tid>>2, p = tid&3;
            const float4* src = (const float4*)(V + base + (size_t)c*NN + jt*64);
            #pragma unroll
            for (int u=0;u<4;u++)
                *(float4*)(sKV + c*SVP + p*16 + u*4) = src[p*4+u];
        }
        __syncthreads();
        #pragma unroll
        for (int kc=0;kc<4;kc++){
            uint32_t Ah[2][4], Al[2][4];
            #pragma unroll
            for (int mt=0;mt<2;mt++){
                int m0 = wm*32+mt*16;
                #pragma unroll
                for (int w=0;w<4;w++){
                    int row = m0 + g + (w&1)*8;
                    int jb  = kc*16 + 2*tg + (w>>1)*8;
                    float2 v = *(const float2*)&sKV[row*SVP + jb];
                    Ah[mt][w]=packbf(v.x,v.y);
                    Al[mt][w]=packbf(v.x-bfhi(v.x), v.y-bfhi(v.y));
                }
            }
            int j2g = jt*32 + kc*8;
            #pragma unroll
            for (int nt=0;nt<6;nt++){
                int n0 = wn*48+nt*8+g;
                uint32_t b0h=__float_as_uint(sS[(2*(j2g+tg))*SSP+n0]);
                uint32_t b0l=__float_as_uint(sS[(2*(j2g+tg)+1)*SSP+n0]);
                uint32_t b1h=__float_as_uint(sS[(2*(j2g+4+tg))*SSP+n0]);
                uint32_t b1l=__float_as_uint(sS[(2*(j2g+4+tg)+1)*SSP+n0]);
                #pragma unroll
                for (int mt=0;mt<2;mt++){
                    float* a = acc[mt*6+nt];
                    mma16(a,Ah[mt],b0h,b1h);
                    mma16(a,Ah[mt],b0l,b1l);
                    mma16(a,Al[mt],b0h,b1h);
                }
            }
        }
    }
    // ---- epilogue ----
    float gm = gamma_p[0];
    #pragma unroll
    for (int mt=0;mt<2;mt++){
        int m0 = wm*32+mt*16;
        #pragma unroll
        for (int nt=0;nt<6;nt++){
            int n0 = wn*48+nt*8 + 2*tg;
            float il0 = sL[n0], il1 = sL[n0+1];
            float* a = acc[mt*6+nt];
            float2 r0 = *(const float2*)(res + base + (size_t)(m0+g)*NN + n0);
            float2 r1 = *(const float2*)(res + base + (size_t)(m0+8+g)*NN + n0);
            *(float2*)(out + base + (size_t)(m0+g)*NN + n0) =
                make_float2(gm*a[0]*il0 + r0.x, gm*a[1]*il1 + r0.y);
            *(float2*)(out + base + (size_t)(m0+8+g)*NN + n0) =
                make_float2(gm*a[2]*il0 + r1.x, gm*a[3]*il1 + r1.y);
        }
    }
}

// ---------------- depthwise 3x3 + bias + gelu ----------------
__global__ void dwconv_k(const float* __restrict__ in, const float* __restrict__ w,
                         const float* __restrict__ bias, float* __restrict__ out){
    int idx = blockIdx.x*blockDim.x + threadIdx.x;
    if (idx >= BB*CC*NN) return;
    int n = idx % NN; int bc = idx / NN; int c = bc % CC;
    int y = n / WW, x = n % WW;
    const float* wp = w + c*9;
    const float* ip = in + (size_t)bc*NN;
    float acc = bias[c];
    #pragma unroll
    for (int ky=0;ky<3;ky++){
        int yy = y+ky-1; if (yy<0||yy>=HH) continue;
        #pragma unroll
        for (int kx=0;kx<3;kx++){
            int xx = x+kx-1; if (xx<0||xx>=WW) continue;
            acc += wp[ky*3+kx]*ip[(size_t)yy*WW+xx];
        }
    }
    out[idx] = gelu_f(acc);
}

// ---------------- transpose [b,c,H,W] -> [b,c,W,H] ----------------
__global__ void transpose_k(const float* __restrict__ in, float* __restrict__ out){
    __shared__ float t[32][33];
    const float* ib = in + (size_t)blockIdx.z*NN;
    float* ob = out + (size_t)blockIdx.z*NN;
    int x = blockIdx.x*32 + threadIdx.x;
    #pragma unroll
    for (int k=0;k<32;k+=8)
        t[threadIdx.y+k][threadIdx.x] = ib[(size_t)(blockIdx.y*32+threadIdx.y+k)*WW + x];
    __syncthreads();
    int x2 = blockIdx.y*32 + threadIdx.x;
    #pragma unroll
    for (int k=0;k<32;k+=8)
        ob[(size_t)(blockIdx.x*32+threadIdx.y+k)*HH + x2] = t[threadIdx.x][threadIdx.y+k];
}

// ---------------- q,k row sum-of-squares ----------------
__global__ void norm_k(const float* __restrict__ q, const float* __restrict__ k){
    int id = blockIdx.x;
    const float* src = (id < BB*CC) ? q : k;
    int bc = id % (BB*CC);
    const float* r = src + (size_t)bc*NN;
    float s=0.f;
    for (int n=threadIdx.x;n<NN;n+=256){ float v=r[n]; s+=v*v; }
    __shared__ float red[256];
    red[threadIdx.x]=s; __syncthreads();
    for (int o=128;o;o>>=1){ if(threadIdx.x<o) red[threadIdx.x]+=red[threadIdx.x+o]; __syncthreads(); }
    if (threadIdx.x==0) g_norm[id]=red[0];
}

__global__ void zero_attn_k(){
    int i = blockIdx.x*blockDim.x+threadIdx.x;
    if (i < BB*NHEADS*32*32) g_attn[i]=0.f;
}

// ---------------- channel-attn gram (chunked atomics) ----------------
#define NCHUNK 32
#define CHUNK (NN/NCHUNK)
__global__ void gram_k(const float* __restrict__ q, const float* __restrict__ k){
    int bg = blockIdx.x; int b=bg/NHEADS, g=bg%NHEADS;
    int n0 = blockIdx.y*CHUNK;
    __shared__ float qs[64][33], ks[64][33];
    int c = threadIdx.x>>3, dg = threadIdx.x&7;
    float a0=0,a1=0,a2=0,a3=0;
    const float* qb = q + ((size_t)(b*CC + g*32))*NN + n0;
    const float* kb = k + ((size_t)(b*CC + g*32))*NN + n0;
    for (int tt=0;tt<CHUNK;tt+=64){
        __syncthreads();
        for (int e=threadIdx.x;e<32*64;e+=256){
            int cc=e>>6, t=e&63;
            qs[t][cc]=qb[(size_t)cc*NN + tt + t];
            ks[t][cc]=kb[(size_t)cc*NN + tt + t];
        }
        __syncthreads();
        #pragma unroll 8
        for (int t=0;t<64;t++){
            float qv=qs[t][c];
            a0+=qv*ks[t][dg];    a1+=qv*ks[t][dg+8];
            a2+=qv*ks[t][dg+16]; a3+=qv*ks[t][dg+24];
        }
    }
    float* ab = g_attn + ((size_t)(bg*32+c))*32;
    atomicAdd(&ab[dg],a0);    atomicAdd(&ab[dg+8],a1);
    atomicAdd(&ab[dg+16],a2); atomicAdd(&ab[dg+24],a3);
}

// ---------------- channel-attn softmax ----------------
__global__ void chsm_k(const float* __restrict__ temp){
    int bg = blockIdx.x; int b=bg/NHEADS, g=bg%NHEADS;
    int c = threadIdx.x>>5, d = threadIdx.x&31;
    float nq = fmaxf(sqrtf(g_norm[b*CC + g*32 + c]), 1e-12f);
    float nk = fmaxf(sqrtf(g_norm[BB*CC + b*CC + g*32 + d]), 1e-12f);
    int idx = (bg*32+c)*32+d;
    float v = g_attn[idx]/(nq*nk)*temp[g];
    float m=v;
    #pragma unroll
    for (int o=16;o;o>>=1) m=fmaxf(m,__shfl_xor_sync(0xffffffffu,m,o));
    float e=expf(v-m), s=e;
    #pragma unroll
    for (int o=16;o;o>>=1) s+=__shfl_xor_sync(0xffffffffu,s,o);
    g_attn[idx]=e/s;
}

// ---------------- mid = attn @ v ----------------
__global__ void attnv_k(const float* __restrict__ v, float* __restrict__ mid){
    __shared__ float4 as4[NHEADS*32*8];
    int b = blockIdx.y;
    int n = blockIdx.x*256 + threadIdx.x;
    const float4* ag = (const float4*)(g_attn + b*NHEADS*32*32);
    for (int i=threadIdx.x;i<NHEADS*32*8;i+=256) as4[i]=ag[i];
    __syncthreads();
    const float* vb = v + (size_t)b*CC*NN + n;
    float* mb = mid + (size_t)b*CC*NN + n;
    #pragma unroll
    for (int g=0;g<NHEADS;g++){
        float vv[32];
        #pragma unroll
        for (int d=0;d<32;d++) vv[d]=vb[(size_t)(g*32+d)*NN];
        #pragma unroll 1
        for (int c=0;c<32;c++){
            float a=0.f;
            #pragma unroll
            for (int d4=0;d4<8;d4++){
                float4 av=as4[(g*32+c)*8+d4];
                a += av.x*vv[d4*4]+av.y*vv[d4*4+1]+av.z*vv[d4*4+2]+av.w*vv[d4*4+3];
            }
            mb[(size_t)(g*32+c)*NN]=a;
        }
    }
}

// =======================================================================
extern "C" void kernel_launch(void* const* d_in, const int* in_sizes, int n_in,
                              void* d_out, int out_size){
    const float* x      =(const float*)d_in[0];
    const float* pw_w   =(const float*)d_in[1];
    const float* dw_w   =(const float*)d_in[2];
    const float* dw_b   =(const float*)d_in[3];
    const float* conv2_w=(const float*)d_in[4];
    const float* conv2_b=(const float*)d_in[5];
    const float* conv0_w=(const float*)d_in[6];
    const float* conv0_b=(const float*)d_in[7];
    const float* att_q_w=(const float*)d_in[8];
    const float* att_k_w=(const float*)d_in[9];
    const float* att_v_w=(const float*)d_in[10];
    const float* att_p_w=(const float*)d_in[11];
    const float* temp   =(const float*)d_in[12];
    const float* row_q_w=(const float*)d_in[13];
    const float* row_k_w=(const float*)d_in[14];
    const float* row_v_w=(const float*)d_in[15];
    const float* row_g  =(const float*)d_in[16];
    const float* col_q_w=(const float*)d_in[17];
    const float* col_k_w=(const float*)d_in[18];
    const float* col_v_w=(const float*)d_in[19];
    const float* col_g  =(const float*)d_in[20];
    const float* conv_w =(const float*)d_in[21];
    const float* conv_b =(const float*)d_in[22];
    float* out=(float*)d_out;

    float *t0,*t1,*x1b,*q,*k,*v,*o1,*o2,*o3;
    cudaGetSymbolAddress((void**)&t0,  g_t0);
    cudaGetSymbolAddress((void**)&t1,  g_t1);
    cudaGetSymbolAddress((void**)&x1b, g_x1);
    cudaGetSymbolAddress((void**)&q,   g_q);
    cudaGetSymbolAddress((void**)&k,   g_k);
    cudaGetSymbolAddress((void**)&v,   g_v);
    cudaGetSymbolAddress((void**)&o1,  g_o1);
    cudaGetSymbolAddress((void**)&o2,  g_o2);
    cudaGetSymbolAddress((void**)&o3,  g_o3);

    const int SM_Q1 = (2*XW_WORDS + 1*2*WW_WORDS)*4;   // 53248
    const int SM_Q2 = (2*XW_WORDS + 2*2*WW_WORDS)*4;   // 71680
    const int SM_Q3 = (2*XW_WORDS + 3*2*WW_WORDS)*4;   // 90112
    const int SM_CM = (2*XW_WORDS + 2*WW_WORDS)*4;     // 53248
    cudaFuncSetAttribute(qkvmma_k<1>, cudaFuncAttributeMaxDynamicSharedMemorySize, SM_Q1);
    cudaFuncSetAttribute(qkvmma_k<2>, cudaFuncAttributeMaxDynamicSharedMemorySize, SM_Q2);
    cudaFuncSetAttribute(qkvmma_k<3>, cudaFuncAttributeMaxDynamicSharedMemorySize, SM_Q3);
    cudaFuncSetAttribute(cmma_k<2,2,false>, cudaFuncAttributeMaxDynamicSharedMemorySize, SM_CM);
    cudaFuncSetAttribute(cmma_k<3,1,true>,  cudaFuncAttributeMaxDynamicSharedMemorySize, SM_CM);
    cudaFuncSetAttribute(fattn_k, cudaFuncAttributeMaxDynamicSharedMemorySize, FA_SMEM);

    dim3 mg(NN/128, BB);
    dim3 cg(NN/256, BB);

    // ---- BSConvU + skip -> x1 ----
    zero_attn_k<<<32,256>>>();
    qkvmma_k<1><<<mg,256,SM_Q1>>>(x, pw_w,nullptr,nullptr, t0,nullptr,nullptr);
    dwconv_k<<<(BB*CC*NN)/256,256>>>(t0, dw_w, dw_b, t1);
    cmma_k<2,2,false><<<mg,256,SM_CM>>>(t1,x,nullptr, conv2_w,conv0_w,nullptr, 64,
                                        conv2_b,conv0_b, x1b);

    // ---- channel self-attention -> o1 ----
    qkvmma_k<3><<<mg,256,SM_Q3>>>(x1b, att_q_w,att_k_w,att_v_w, q,k,v);
    norm_k<<<2*BB*CC,256>>>(q,k);
    gram_k<<<dim3(BB*NHEADS,NCHUNK),256>>>(q,k);
    chsm_k<<<BB*NHEADS,1024>>>(temp);
    attnv_k<<<cg,256>>>(v, t0);
    qkvmma_k<1><<<mg,256,SM_Q1>>>(t0, att_p_w,nullptr,nullptr, o1,nullptr,nullptr);

    // ---- row attention -> o2 ----
    qkvmma_k<2><<<mg,256,SM_Q2>>>(x1b, row_q_w,row_k_w,nullptr, q,k,nullptr);
    qkvmma_k<1><<<mg,256,SM_Q1>>>(o1, row_v_w,nullptr,nullptr, v,nullptr,nullptr);
    fattn_k<<<BB*HH,256,FA_SMEM>>>(q,k,v,x1b,row_g,o2);

    // ---- col attention (transposed) -> o3 ----
    transpose_k<<<dim3(6,6,BB*CC),dim3(32,8)>>>(x1b, t1);
    transpose_k<<<dim3(6,6,BB*CC),dim3(32,8)>>>(o1,  t0);
    qkvmma_k<2><<<mg,256,SM_Q2>>>(t1, col_q_w,col_k_w,nullptr, q,k,nullptr);
    qkvmma_k<1><<<mg,256,SM_Q1>>>(t0, col_v_w,nullptr,nullptr, v,nullptr,nullptr);
    fattn_k<<<BB*WW,256,FA_SMEM>>>(q,k,v,t1,col_g,t0);
    transpose_k<<<dim3(6,6,BB*CC),dim3(32,8)>>>(t0, o3);

    // ---- fuse ----
    cmma_k<3,1,true><<<mg,256,SM_CM>>>(o1,o2,o3, conv_w,conv_w+64,conv_w+128, 192,
                                       conv_b,nullptr, out);
}